// round 12
// baseline (speedup 1.0000x reference)
#include <cuda_runtime.h>
#include <cuda_bf16.h>
#include <math.h>
#include <stdint.h>

#define NNODES 100000
#define NEDGES 100000
#define D      128
#define NPAIRS 64
#define NTYPES 14
#define NSLOTS 67   // 0:in2 1:seg2 2:meta 3..6:ctr 7..62:edge 63..66:ctr2

#define SCAN_N   (NTYPES * NNODES)
#define SCAN_BLK 4096
#define SCAN_NBLK ((SCAN_N + SCAN_BLK - 1) / SCAN_BLK)

// ---------------- static device scratch ----------------
__device__ float    g_feat[NNODES * D];
__device__ float    g_res [NNODES * D];
__device__ float    g_tmp [NNODES * D];
__device__ uint32_t g_Ahi [NNODES * NPAIRS];
__device__ uint32_t g_Alo [NNODES * NPAIRS];
__device__ uint32_t g_Whi [NSLOTS * D * NPAIRS];   // pair-interleaved layout
__device__ uint32_t g_Wlo [NSLOTS * D * NPAIRS];
__device__ float    g_H  [NNODES * D];
__device__ int g_deg [SCAN_N];
__device__ int g_off [SCAN_N];
__device__ int g_cur [SCAN_N];
__device__ int g_dst [NTYPES * NEDGES];
__device__ int g_bsum[512];
__device__ int g_rcnt[NTYPES];              // per-type live-row counts
__device__ int g_rlist[NTYPES * NNODES];    // per-type compacted src lists

// ---------------- generic helpers ----------------
__device__ __forceinline__ uint32_t pack_bf16x2(float e0, float e1) {
    uint32_t r;
    asm("cvt.rn.bf16x2.f32 %0, %1, %2;" : "=r"(r) : "f"(e1), "f"(e0));
    return r;
}
__device__ __forceinline__ void split_pair(float x0, float x1,
                                           uint32_t& hi, uint32_t& lo) {
    hi = pack_bf16x2(x0, x1);
    float h0 = __uint_as_float(hi << 16);
    float h1 = __uint_as_float(hi & 0xFFFF0000u);
    lo = pack_bf16x2(x0 - h0, x1 - h1);
}
__device__ __forceinline__ void mma_bf16(float* d, const uint32_t* a, const uint32_t* b) {
    asm volatile(
        "mma.sync.aligned.m16n8k16.row.col.f32.bf16.bf16.f32 "
        "{%0,%1,%2,%3}, {%4,%5,%6,%7}, {%8,%9}, {%0,%1,%2,%3};"
        : "+f"(d[0]), "+f"(d[1]), "+f"(d[2]), "+f"(d[3])
        : "r"(a[0]), "r"(a[1]), "r"(a[2]), "r"(a[3]), "r"(b[0]), "r"(b[1]));
}
__device__ __forceinline__ void red_v4(float* p, float4 v) {
    asm volatile("red.global.add.v4.f32 [%0], {%1, %2, %3, %4};"
                 :: "l"(p), "f"(v.x), "f"(v.y), "f"(v.z), "f"(v.w) : "memory");
}
__device__ __forceinline__ void cp16(uint32_t dst_smem, const void* src) {
    asm volatile("cp.async.ca.shared.global [%0], [%1], 16;" :: "r"(dst_smem), "l"(src));
}
__device__ __forceinline__ uint32_t smem_u32(const void* p) {
    uint32_t a;
    asm("{ .reg .u64 t; cvta.to.shared.u64 t, %1; cvt.u32.u64 %0, t; }" : "=r"(a) : "l"(p));
    return a;
}

// ---------------- CSR build ----------------
__global__ void zero_deg_kernel(int* deg, int* rcnt) {
    int i = blockIdx.x * blockDim.x + threadIdx.x;
    if (i < SCAN_N) deg[i] = 0;
    if (i < NTYPES) rcnt[i] = 0;
}
// edge-major: one thread per edge, coalesced int4 x7 index reads
__global__ void deg_kernel(const int* __restrict__ indexes,
                           const int* __restrict__ mask, int* __restrict__ deg) {
    int e = blockIdx.x * blockDim.x + threadIdx.x;
    if (e >= NEDGES) return;
    int4 v[7];
    const int4* row = reinterpret_cast<const int4*>(indexes + e * 28);
    #pragma unroll
    for (int i = 0; i < 7; i++) v[i] = __ldg(row + i);
    const int* vi = reinterpret_cast<const int*>(v);
    #pragma unroll
    for (int t = 0; t < NTYPES; t++) {
        if (e < __ldg(mask + t)) {
            int src = vi[2 * t + 1];
            atomicAdd(&deg[t * NNODES + src], 1);
        }
    }
}
__global__ void rowlist_kernel(const int* __restrict__ deg,
                               int* __restrict__ rcnt, int* __restrict__ rlist) {
    int i = blockIdx.x * blockDim.x + threadIdx.x;
    if (i >= SCAN_N) return;
    if (deg[i] > 0) {
        int t = i / NNODES;
        int src = i - t * NNODES;
        int pos = atomicAdd(&rcnt[t], 1);
        rlist[t * NNODES + pos] = src;
    }
}
__global__ void scan1_kernel(const int* __restrict__ deg, int* __restrict__ off,
                             int* __restrict__ bsum) {
    __shared__ int warp_tot[8];
    int b = blockIdx.x, tid = threadIdx.x;
    int base = b * SCAN_BLK + tid * 16;
    int v[16];
    int run = 0;
    #pragma unroll
    for (int i = 0; i < 16; i++) {
        int idx = base + i;
        int t = (idx < SCAN_N) ? deg[idx] : 0;
        v[i] = run;
        run += t;
    }
    int lane = tid & 31, w = tid >> 5;
    int x = run;
    #pragma unroll
    for (int o = 1; o < 32; o <<= 1) {
        int y = __shfl_up_sync(0xffffffffu, x, o);
        if (lane >= o) x += y;
    }
    if (lane == 31) warp_tot[w] = x;
    __syncthreads();
    int woff = 0;
    for (int i = 0; i < w; i++) woff += warp_tot[i];
    int excl = x - run + woff;
    #pragma unroll
    for (int i = 0; i < 16; i++)
        if (base + i < SCAN_N) off[base + i] = v[i] + excl;
    if (tid == 255) bsum[b] = excl + run;
}
__global__ void scan2_kernel(int* bsum, int n) {
    __shared__ int sm[512];
    int tid = threadIdx.x;
    int v = (tid < n) ? bsum[tid] : 0;
    sm[tid] = v;
    __syncthreads();
    for (int o = 1; o < 512; o <<= 1) {
        int t = (tid >= o) ? sm[tid - o] : 0;
        __syncthreads();
        sm[tid] += t;
        __syncthreads();
    }
    if (tid < n) bsum[tid] = sm[tid] - v;
}
__global__ void scan3_kernel(int* __restrict__ off, const int* __restrict__ bsum,
                             int* __restrict__ cur) {
    int i = blockIdx.x * blockDim.x + threadIdx.x;
    if (i >= SCAN_N) return;
    int o = off[i] + bsum[i / SCAN_BLK];
    off[i] = o;
    cur[i] = o;
}
__global__ void fill_kernel(const int* __restrict__ indexes,
                            const int* __restrict__ mask,
                            int* __restrict__ cur, int* __restrict__ dstA) {
    int e = blockIdx.x * blockDim.x + threadIdx.x;
    if (e >= NEDGES) return;
    int4 v[7];
    const int4* row = reinterpret_cast<const int4*>(indexes + e * 28);
    #pragma unroll
    for (int i = 0; i < 7; i++) v[i] = __ldg(row + i);
    const int* vi = reinterpret_cast<const int*>(v);
    #pragma unroll
    for (int t = 0; t < NTYPES; t++) {
        if (e < __ldg(mask + t)) {
            int src = vi[2 * t + 1];
            int dst = vi[2 * t];
            int pos = atomicAdd(&cur[t * NNODES + src], 1);
            dstA[pos] = dst;
        }
    }
}

// ---------------- pre-split weights (PAIR-INTERLEAVED gmem layout) -------------
__global__ void split_w_kernel(const float* __restrict__ in2,
                               const float* __restrict__ seg2,
                               const float* __restrict__ meta,
                               const float* __restrict__ ctr,
                               const float* __restrict__ edge,
                               const float* __restrict__ ctr2,
                               uint32_t* __restrict__ Whi,
                               uint32_t* __restrict__ Wlo) {
    int idx = blockIdx.x * blockDim.x + threadIdx.x;
    if (idx >= NSLOTS * D * NPAIRS) return;
    int slot = idx / (D * NPAIRS);
    int r    = idx - slot * (D * NPAIRS);
    int c    = r >> 6;
    int ip   = r & 63;
    int g  = ip >> 3;
    int w  = ip & 7;
    int qk = w >> 1;
    int j  = w & 1;
    int p  = 8 * g + qk + 4 * j;
    int k0 = 2 * p;
    float x0, x1;
    if      (slot == 0) { x0 = in2 [c * D + k0]; x1 = in2 [c * D + k0 + 1]; }
    else if (slot == 1) { x0 = seg2[c * D + k0]; x1 = seg2[c * D + k0 + 1]; }
    else if (slot == 2) { x0 = meta[c * 132 + k0]; x1 = meta[c * 132 + k0 + 1]; }
    else if (slot < 7)  { const float* wm = ctr  + (long)(slot - 3)  * D * D;
                          x0 = wm[c * D + k0]; x1 = wm[c * D + k0 + 1]; }
    else if (slot < 63) { const float* wm = edge + (long)(slot - 7)  * D * D;
                          x0 = wm[c * D + k0]; x1 = wm[c * D + k0 + 1]; }
    else                { const float* wm = ctr2 + (long)(slot - 63) * D * D;
                          x0 = wm[c * D + k0]; x1 = wm[c * D + k0 + 1]; }
    uint32_t hi, lo;
    split_pair(x0, x1, hi, lo);
    Whi[idx] = hi;
    Wlo[idx] = lo;
}

// ---------------- lin1 ----------------
__global__ void lin1_kernel(const float* __restrict__ nodes, int off,
                            const float* __restrict__ W1, const float* __restrict__ b1,
                            uint32_t* __restrict__ Ahi, uint32_t* __restrict__ Alo) {
    int idx = blockIdx.x * blockDim.x + threadIdx.x;
    if (idx >= NNODES * NPAIRS) return;
    int n = idx >> 6;
    int p = idx & 63;
    int j0 = 2 * p;
    float x0 = nodes[n * 8 + off];
    float x1 = nodes[n * 8 + off + 1];
    float v0 = fmaxf(fmaf(x0, W1[j0 * 2],     fmaf(x1, W1[j0 * 2 + 1], b1[j0])),     0.0f);
    float v1 = fmaxf(fmaf(x0, W1[j0 * 2 + 2], fmaf(x1, W1[j0 * 2 + 3], b1[j0 + 1])), 0.0f);
    uint32_t hi, lo;
    split_pair(v0, v1, hi, lo);
    Ahi[idx] = hi;
    Alo[idx] = lo;
}

// ---------------- GEMM (init/meta/ctr2): interleaved W, LDS.64 B-frags --------
#define TC_THREADS 256
#define SW_STR     72
#define TC_SMEM    (2 * D * SW_STR * 4)
#define TC_GRID    296

__global__ void __launch_bounds__(TC_THREADS, 2)
gemm_tc_kernel(const uint32_t* __restrict__ Ahi, const uint32_t* __restrict__ Alo,
               const uint32_t* __restrict__ Whi, const uint32_t* __restrict__ Wlo,
               float* __restrict__ C, int nrows) {
    extern __shared__ uint32_t sm[];
    uint32_t* sWhi = sm;
    uint32_t* sWlo = sm + D * SW_STR;
    int tid = threadIdx.x;

    for (int idx = tid; idx < D * NPAIRS; idx += TC_THREADS) {
        int c = idx >> 6;
        int ip = idx & 63;
        sWhi[c * SW_STR + ip] = Whi[idx];
        sWlo[c * SW_STR + ip] = Wlo[idx];
    }
    __syncthreads();

    int wid  = tid >> 5;
    int lane = tid & 31;
    int rgrp = wid >> 1;
    int cgrp = wid & 1;
    int qr = lane >> 2;
    int qk = lane & 3;

    int ntiles = (nrows + 127) / 128;
    for (int tile = blockIdx.x; tile < ntiles; tile += gridDim.x) {
        int rbase = tile * 128 + rgrp * 32;
        int r00 = rbase + qr;
        int r01 = rbase + qr + 8;
        int r10 = rbase + 16 + qr;
        int r11 = rbase + 16 + qr + 8;
        bool v00 = r00 < nrows, v01 = r01 < nrows;
        bool v10 = r10 < nrows, v11 = r11 < nrows;

        float acc[2][8][4];
        #pragma unroll
        for (int s = 0; s < 2; s++)
            #pragma unroll
            for (int nt = 0; nt < 8; nt++)
                #pragma unroll
                for (int j = 0; j < 4; j++) acc[s][nt][j] = 0.0f;

        #pragma unroll
        for (int kt = 0; kt < 8; kt++) {
            int p0 = kt * 8 + qk;
            int p1 = p0 + 4;
            uint32_t ah0[4], al0[4], ah1[4], al1[4];
            ah0[0] = v00 ? Ahi[(long)r00 * NPAIRS + p0] : 0u;
            ah0[1] = v01 ? Ahi[(long)r01 * NPAIRS + p0] : 0u;
            ah0[2] = v00 ? Ahi[(long)r00 * NPAIRS + p1] : 0u;
            ah0[3] = v01 ? Ahi[(long)r01 * NPAIRS + p1] : 0u;
            al0[0] = v00 ? Alo[(long)r00 * NPAIRS + p0] : 0u;
            al0[1] = v01 ? Alo[(long)r01 * NPAIRS + p0] : 0u;
            al0[2] = v00 ? Alo[(long)r00 * NPAIRS + p1] : 0u;
            al0[3] = v01 ? Alo[(long)r01 * NPAIRS + p1] : 0u;
            ah1[0] = v10 ? Ahi[(long)r10 * NPAIRS + p0] : 0u;
            ah1[1] = v11 ? Ahi[(long)r11 * NPAIRS + p0] : 0u;
            ah1[2] = v10 ? Ahi[(long)r10 * NPAIRS + p1] : 0u;
            ah1[3] = v11 ? Ahi[(long)r11 * NPAIRS + p1] : 0u;
            al1[0] = v10 ? Alo[(long)r10 * NPAIRS + p0] : 0u;
            al1[1] = v11 ? Alo[(long)r11 * NPAIRS + p0] : 0u;
            al1[2] = v10 ? Alo[(long)r10 * NPAIRS + p1] : 0u;
            al1[3] = v11 ? Alo[(long)r11 * NPAIRS + p1] : 0u;

            #pragma unroll
            for (int nt = 0; nt < 8; nt++) {
                int n = cgrp * 64 + nt * 8 + qr;
                int o = n * SW_STR + kt * 8 + 2 * qk;
                uint2 BH = *reinterpret_cast<const uint2*>(&sWhi[o]);
                uint2 BL = *reinterpret_cast<const uint2*>(&sWlo[o]);
                uint32_t bh[2] = { BH.x, BH.y };
                uint32_t bl[2] = { BL.x, BL.y };
                mma_bf16(acc[0][nt], ah0, bh);
                mma_bf16(acc[0][nt], al0, bh);
                mma_bf16(acc[0][nt], ah0, bl);
                mma_bf16(acc[1][nt], ah1, bh);
                mma_bf16(acc[1][nt], al1, bh);
                mma_bf16(acc[1][nt], ah1, bl);
            }
        }

        #pragma unroll
        for (int nt = 0; nt < 8; nt++) {
            int col = cgrp * 64 + nt * 8 + 2 * qk;
            if (v00) *reinterpret_cast<float2*>(C + (long)r00 * D + col) =
                         make_float2(acc[0][nt][0], acc[0][nt][1]);
            if (v01) *reinterpret_cast<float2*>(C + (long)r01 * D + col) =
                         make_float2(acc[0][nt][2], acc[0][nt][3]);
            if (v10) *reinterpret_cast<float2*>(C + (long)r10 * D + col) =
                         make_float2(acc[1][nt][0], acc[1][nt][1]);
            if (v11) *reinterpret_cast<float2*>(C + (long)r11 * D + col) =
                         make_float2(acc[1][nt][2], acc[1][nt][3]);
        }
    }
}

// ---------------- persistent fused message-passing layer ----------------
// grid=148, 512 thr (16 warps). Slots OUTER, tiles INNER (block tile = 256 rows).
// Edge slots iterate COMPACTED per-type row lists (only srcs with deg>0, ~63%).
#define MPP_THREADS 512
#define MPP_GRID    148
#define WP_STR      72
#define W_TILE      (D * WP_STR)
#define STG_STR     72
#define MPP_SMEM    ((4 * W_TILE + 16 * 16 * STG_STR) * 4)

__global__ void __launch_bounds__(MPP_THREADS, 1)
mp_p_kernel(const uint32_t* __restrict__ Ahi, const uint32_t* __restrict__ Alo,
            const uint32_t* __restrict__ Whi, const uint32_t* __restrict__ Wlo,
            int layer,
            const int* __restrict__ off, const int* __restrict__ deg,
            const int* __restrict__ dstA,
            const int* __restrict__ rcnt, const int* __restrict__ rlist,
            float* __restrict__ tmp, int nrows) {
    extern __shared__ uint32_t sm[];
    float* stage = reinterpret_cast<float*>(sm + 4 * W_TILE);
    uint32_t sbase = smem_u32(sm);

    int tid  = threadIdx.x;
    int wid  = tid >> 5;
    int lane = tid & 31;
    int rg = wid >> 1;
    int ch = wid & 1;
    int qr = lane >> 2;
    int qk = lane & 3;

    auto slot_of = [&](int s) {
        return (s == 0) ? (3 + layer) : (7 + layer * NTYPES + s - 1);
    };
    auto cp_w = [&](int s, int b) {
        const uint32_t* wh = Whi + (long)slot_of(s) * D * NPAIRS;
        const uint32_t* wl = Wlo + (long)slot_of(s) * D * NPAIRS;
        uint32_t bh = sbase + (uint32_t)(2 * b)     * W_TILE * 4u;
        uint32_t bl = sbase + (uint32_t)(2 * b + 1) * W_TILE * 4u;
        for (int i = tid * 4; i < D * NPAIRS; i += MPP_THREADS * 4) {
            int c = i >> 6, ip = i & 63;
            uint32_t o = (uint32_t)(c * WP_STR + ip) * 4u;
            cp16(bh + o, wh + i);
            cp16(bl + o, wl + i);
        }
        asm volatile("cp.async.commit_group;" ::: "memory");
    };

    cp_w(0, 0);

    for (int s = 0; s < 15; s++) {
        asm volatile("cp.async.wait_group 0;" ::: "memory");
        __syncthreads();
        if (s < 14) cp_w(s + 1, (s + 1) & 1);

        const uint32_t* sWhi = sm + (size_t)(2 * (s & 1))     * W_TILE;
        const uint32_t* sWlo = sm + (size_t)(2 * (s & 1) + 1) * W_TILE;
        int t = s - 1;
        int m = (s == 0) ? nrows : __ldg(rcnt + t);
        const int* rl = rlist + (long)(s == 0 ? 0 : t) * NNODES;
        int ntl = (m + 255) >> 8;

        for (int tile = blockIdx.x; tile < ntl; tile += MPP_GRID) {
            int rb = tile * 256 + rg * 32;
            int i00 = rb + qr;
            int i01 = rb + qr + 8;
            int i10 = rb + 16 + qr;
            int i11 = rb + 16 + qr + 8;
            bool v00 = i00 < m, v01 = i01 < m;
            bool v10 = i10 < m, v11 = i11 < m;
            int r00, r01, r10, r11;
            if (s == 0) {
                r00 = i00; r01 = i01; r10 = i10; r11 = i11;
            } else {
                r00 = v00 ? __ldg(rl + i00) : 0;
                r01 = v01 ? __ldg(rl + i01) : 0;
                r10 = v10 ? __ldg(rl + i10) : 0;
                r11 = v11 ? __ldg(rl + i11) : 0;
            }

            float acc[2][8][4];
            #pragma unroll
            for (int s2 = 0; s2 < 2; s2++)
                #pragma unroll
                for (int nt = 0; nt < 8; nt++)
                    #pragma unroll
                    for (int j = 0; j < 4; j++) acc[s2][nt][j] = 0.0f;

            #pragma unroll 2
            for (int kt = 0; kt < 8; kt++) {
                int p0 = kt * 8 + qk;
                int p1 = p0 + 4;
                uint32_t ah0[4], al0[4], ah1[4], al1[4];
                ah0[0] = v00 ? Ahi[(long)r00 * NPAIRS + p0] : 0u;
                ah0[1] = v01 ? Ahi[(long)r01 * NPAIRS + p0] : 0u;
                ah0[2] = v00 ? Ahi[(long)r00 * NPAIRS + p1] : 0u;
                ah0[3] = v01 ? Ahi[(long)r01 * NPAIRS + p1] : 0u;
                al0[0] = v00 ? Alo[(long)r00 * NPAIRS + p0] : 0u;
                al0[1] = v01 ? Alo[(long)r01 * NPAIRS + p0] : 0u;
                al0[2] = v00 ? Alo[(long)r00 * NPAIRS + p1] : 0u;
                al0[3] = v01 ? Alo[(long)r01 * NPAIRS + p1] : 0u;
                ah1[0] = v10 ? Ahi[(long)r10 * NPAIRS + p0] : 0u;
                ah1[1] = v11 ? Ahi[(long)r11 * NPAIRS + p0] : 0u;
                ah1[2] = v10 ? Ahi[(long)r10 * NPAIRS + p1] : 0u;
                ah1[3] = v11 ? Ahi[(long)r11 * NPAIRS + p1] : 0u;
                al1[0] = v10 ? Alo[(long)r10 * NPAIRS + p0] : 0u;
                al1[1] = v11 ? Alo[(long)r11 * NPAIRS + p0] : 0u;
                al1[2] = v10 ? Alo[(long)r10 * NPAIRS + p1] : 0u;
                al1[3] = v11 ? Alo[(long)r11 * NPAIRS + p1] : 0u;

                #pragma unroll
                for (int nt = 0; nt < 8; nt++) {
                    int n = ch * 64 + nt * 8 + qr;
                    int o = n * WP_STR + kt * 8 + 2 * qk;
                    uint2 BH = *reinterpret_cast<const uint2*>(&sWhi[o]);
                    uint2 BL = *reinterpret_cast<const uint2*>(&sWlo[o]);
                    uint32_t bh[2] = { BH.x, BH.y };
                    uint32_t bl[2] = { BL.x, BL.y };
                    mma_bf16(acc[0][nt], ah0, bh);
                    mma_bf16(acc[0][nt], al0, bh);
                    mma_bf16(acc[0][nt], ah0, bl);
                    mma_bf16(acc[1][nt], ah1, bh);
                    mma_bf16(acc[1][nt], al1, bh);
                    mma_bf16(acc[1][nt], ah1, bl);
                }
            }

            float* st = stage + wid * (16 * STG_STR);
            #pragma unroll
            for (int s2 = 0; s2 < 2; s2++) {
                #pragma unroll
                for (int nt = 0; nt < 8; nt++) {
                    int c2 = nt * 8 + 2 * qk;
                    *reinterpret_cast<float2*>(&st[qr * STG_STR + c2]) =
                        make_float2(acc[s2][nt][0], acc[s2][nt][1]);
                    *reinterpret_cast<float2*>(&st[(qr + 8) * STG_STR + c2]) =
                        make_float2(acc[s2][nt][2], acc[s2][nt][3]);
                }
                __syncwarp();

                int ibase = rb + s2 * 16;
                int colg = ch * 64 + (lane & 15) * 4;
                #pragma unroll
                for (int rr = 0; rr < 16; rr += 2) {
                    int lr  = rr + (lane >> 4);
                    int idx = ibase + lr;
                    float4 v = *reinterpret_cast<float4*>(
                        &st[lr * STG_STR + (lane & 15) * 4]);
                    if (idx < m) {
                        if (s == 0) {
                            red_v4(tmp + (long)idx * D + colg, v);
                        } else {
                            int row = __ldg(rl + idx);
                            long key = (long)t * NNODES + row;
                            int o0 = __ldg(off + key);
                            int dg = __ldg(deg + key);
                            for (int e = 0; e < dg; e++) {
                                int d = __ldg(dstA + o0 + e);
                                red_v4(tmp + (long)d * D + colg, v);
                            }
                        }
                    }
                }
                __syncwarp();
            }
        }
    }
}

// ---------------- GroupNorm helpers ----------------
__device__ __forceinline__ float warp_sum(float v) {
    #pragma unroll
    for (int o = 16; o > 0; o >>= 1) v += __shfl_xor_sync(0xffffffffu, v, o);
    return v;
}
__device__ __forceinline__ void store_split4(uint32_t* Ahi, uint32_t* Alo,
                                             int row, int lane, float4 y) {
    uint32_t h0, l0, h1, l1;
    split_pair(y.x, y.y, h0, l0);
    split_pair(y.z, y.w, h1, l1);
    *reinterpret_cast<uint2*>(Ahi + (long)row * NPAIRS + lane * 2) = make_uint2(h0, h1);
    *reinterpret_cast<uint2*>(Alo + (long)row * NPAIRS + lane * 2) = make_uint2(l0, l1);
}

__global__ void gn_kernel(const float* __restrict__ in,
                          const float* __restrict__ g, const float* __restrict__ b,
                          const float* __restrict__ resid,
                          float* __restrict__ out1, float* __restrict__ out2,
                          uint32_t* __restrict__ Ahi, uint32_t* __restrict__ Alo,
                          float* __restrict__ zbuf,
                          int do_relu) {
    int warp = (blockIdx.x * blockDim.x + threadIdx.x) >> 5;
    int lane = threadIdx.x & 31;
    if (warp >= NNODES) return;
    const float4 x = *reinterpret_cast<const float4*>(in + (long)warp * D + lane * 4);
    float s  = x.x + x.y + x.z + x.w;
    float ss = x.x * x.x + x.y * x.y + x.z * x.z + x.w * x.w;
    s  = warp_sum(s);
    ss = warp_sum(ss);
    float m   = s * (1.0f / 128.0f);
    float var = ss * (1.0f / 128.0f) - m * m;
    float inv = rsqrtf(var + 1e-5f);
    float4 gg = *reinterpret_cast<const float4*>(g + lane * 4);
    float4 bb = *reinterpret_cast<const float4*>(b + lane * 4);
    float4 y;
    y.x = fmaf((x.x - m) * inv, gg.x, bb.x);
    y.y = fmaf((x.y - m) * inv, gg.y, bb.y);
    y.z = fmaf((x.z - m) * inv, gg.z, bb.z);
    y.w = fmaf((x.w - m) * inv, gg.w, bb.w);
    if (resid) {
        float4 r = *reinterpret_cast<const float4*>(resid + (long)warp * D + lane * 4);
        y.x += r.x; y.y += r.y; y.z += r.z; y.w += r.w;
    }
    if (do_relu) {
        y.x = fmaxf(y.x, 0.0f); y.y = fmaxf(y.y, 0.0f);
        y.z = fmaxf(y.z, 0.0f); y.w = fmaxf(y.w, 0.0f);
    }
    if (out1)
        *reinterpret_cast<float4*>(out1 + (long)warp * D + lane * 4) = y;
    if (out2)
        *reinterpret_cast<float4*>(out2 + (long)warp * D + lane * 4) = y;
    if (Ahi) store_split4(Ahi, Alo, warp, lane, y);
    if (zbuf)
        *reinterpret_cast<float4*>(zbuf + (long)warp * D + lane * 4) =
            make_float4(0.f, 0.f, 0.f, 0.f);
}

__global__ void gn2_kernel(const float* __restrict__ inA,
                           const float* __restrict__ gA, const float* __restrict__ bA,
                           const float* __restrict__ inB,
                           const float* __restrict__ gB, const float* __restrict__ bB,
                           uint32_t* __restrict__ Ahi, uint32_t* __restrict__ Alo) {
    int warp = (blockIdx.x * blockDim.x + threadIdx.x) >> 5;
    int lane = threadIdx.x & 31;
    if (warp >= NNODES) return;
    const float4 xa = *reinterpret_cast<const float4*>(inA + (long)warp * D + lane * 4);
    const float4 xb = *reinterpret_cast<const float4*>(inB + (long)warp * D + lane * 4);
    float sa  = xa.x + xa.y + xa.z + xa.w;
    float ssa = xa.x * xa.x + xa.y * xa.y + xa.z * xa.z + xa.w * xa.w;
    float sb  = xb.x + xb.y + xb.z + xb.w;
    float ssb = xb.x * xb.x + xb.y * xb.y + xb.z * xb.z + xb.w * xb.w;
    sa = warp_sum(sa); ssa = warp_sum(ssa);
    sb = warp_sum(sb); ssb = warp_sum(ssb);
    float ma = sa * (1.0f / 128.0f);
    float mb = sb * (1.0f / 128.0f);
    float ia = rsqrtf(ssa * (1.0f / 128.0f) - ma * ma + 1e-5f);
    float ib = rsqrtf(ssb * (1.0f / 128.0f) - mb * mb + 1e-5f);
    float4 ga4 = *reinterpret_cast<const float4*>(gA + lane * 4);
    float4 ba4 = *reinterpret_cast<const float4*>(bA + lane * 4);
    float4 gb4 = *reinterpret_cast<const float4*>(gB + lane * 4);
    float4 bb4 = *reinterpret_cast<const float4*>(bB + lane * 4);
    float4 y;
    y.x = fmaf((xa.x - ma) * ia, ga4.x, ba4.x) + fmaf((xb.x - mb) * ib, gb4.x, bb4.x);
    y.y = fmaf((xa.y - ma) * ia, ga4.y, ba4.y) + fmaf((xb.y - mb) * ib, gb4.y, bb4.y);
    y.z = fmaf((xa.z - ma) * ia, ga4.z, ba4.z) + fmaf((xb.z - mb) * ib, gb4.z, bb4.z);
    y.w = fmaf((xa.w - ma) * ia, ga4.w, ba4.w) + fmaf((xb.w - mb) * ib, gb4.w, bb4.w);
    y.x = fmaxf(y.x, 0.0f); y.y = fmaxf(y.y, 0.0f);
    y.z = fmaxf(y.z, 0.0f); y.w = fmaxf(y.w, 0.0f);
    store_split4(Ahi, Alo, warp, lane, y);
}

// ---------------- rank-4 update ----------------
__global__ void rank4_kernel(const float* __restrict__ nodes,
                             const float* __restrict__ metaW,
                             float* __restrict__ out) {
    int idx = blockIdx.x * blockDim.x + threadIdx.x;
    if (idx >= NNODES * D) return;
    int n = idx >> 7;
    int c = idx & 127;
    const float* wr = metaW + c * 132 + 128;
    const float* nd = nodes + n * 8 + 4;
    float s = fmaf(nd[0], wr[0], fmaf(nd[1], wr[1], fmaf(nd[2], wr[2], nd[3] * wr[3])));
    out[idx] += s;
}

// ---------------- final output ----------------
__global__ void copy_out_kernel(const float* __restrict__ feat,
                                const float* __restrict__ nodes,
                                float* __restrict__ out) {
    int idx = blockIdx.x * blockDim.x + threadIdx.x;
    const int F = NNODES * D;
    if (idx < F) {
        out[idx] = feat[idx];
    } else if (idx < F + NNODES * 2) {
        int j = idx - F;
        int n = j >> 1;
        int c = j & 1;
        out[idx] = nodes[n * 8 + c];
    }
}

// ---------------- host launcher ----------------
extern "C" void kernel_launch(void* const* d_in, const int* in_sizes, int n_in,
                              void* d_out, int out_size) {
    const float* nodes   = (const float*)d_in[0];
    const int*   indexes = (const int*)  d_in[1];
    const int*   mask    = (const int*)  d_in[2];
    const float* in1_W   = (const float*)d_in[3];
    const float* in1_b   = (const float*)d_in[4];
    const float* in2_W   = (const float*)d_in[5];
    const float* in_g    = (const float*)d_in[6];
    const float* in_bg   = (const float*)d_in[7];
    const float* seg1_W  = (const float*)d_in[8];
    const float* seg1_b  = (const float*)d_in[9];
    const float* seg2_W  = (const float*)d_in[10];
    const float* seg_g   = (const float*)d_in[11];
    const float* seg_bg  = (const float*)d_in[12];
    const float* meta_W  = (const float*)d_in[13];
    const float* meta_g  = (const float*)d_in[14];
    const float* meta_bg = (const float*)d_in[15];
    const float* ctr_W   = (const float*)d_in[16];
    const float* edge_W  = (const float*)d_in[17];
    const float* norm_g  = (const float*)d_in[18];
    const float* norm_bg = (const float*)d_in[19];
    const float* ctr2_W  = (const float*)d_in[20];
    const float* ctr2_g  = (const float*)d_in[21];
    const float* ctr2_bg = (const float*)d_in[22];
    float* out = (float*)d_out;

    float *feat, *res, *tmp;
    uint32_t *Whi, *Wlo, *Ahi, *Alo;
    int *deg, *off, *cur, *dstA, *bsum, *rcnt, *rlist;
    cudaGetSymbolAddress((void**)&feat, g_feat);
    cudaGetSymbolAddress((void**)&res,  g_res);
    cudaGetSymbolAddress((void**)&tmp,  g_tmp);
    cudaGetSymbolAddress((void**)&Whi,  g_Whi);
    cudaGetSymbolAddress((void**)&Wlo,  g_Wlo);
    cudaGetSymbolAddress((void**)&Ahi,  g_Ahi);
    cudaGetSymbolAddress((void**)&Alo,  g_Alo);
    cudaGetSymbolAddress((void**)&deg,  g_deg);
    cudaGetSymbolAddress((void**)&off,  g_off);
    cudaGetSymbolAddress((void**)&cur,  g_cur);
    cudaGetSymbolAddress((void**)&dstA, g_dst);
    cudaGetSymbolAddress((void**)&bsum, g_bsum);
    cudaGetSymbolAddress((void**)&rcnt, g_rcnt);
    cudaGetSymbolAddress((void**)&rlist,g_rlist);
    float* Hbuf;
    cudaGetSymbolAddress((void**)&Hbuf, g_H);

    cudaFuncSetAttribute(gemm_tc_kernel,
                         cudaFuncAttributeMaxDynamicSharedMemorySize, TC_SMEM);
    cudaFuncSetAttribute(mp_p_kernel,
                         cudaFuncAttributeMaxDynamicSharedMemorySize, MPP_SMEM);

    const int lin_grid = (NNODES * NPAIRS + 255) / 256;
    const int gn_grid  = (NNODES * 32 + 255) / 256;
    const int sw_grid  = (NSLOTS * D * NPAIRS + 255) / 256;
    const int r4_grid  = (NNODES * D + 255) / 256;
    const int e_grid   = (NEDGES + 255) / 256;
    const int zn_grid  = (SCAN_N + 255) / 256;

    auto sWp = [&](int s) { return Whi + (long)s * D * NPAIRS; };
    auto sLp = [&](int s) { return Wlo + (long)s * D * NPAIRS; };

    // ---- CSR build + per-type row lists ----
    zero_deg_kernel<<<zn_grid, 256>>>(deg, rcnt);
    deg_kernel<<<e_grid, 256>>>(indexes, mask, deg);
    scan1_kernel<<<SCAN_NBLK, 256>>>(deg, off, bsum);
    scan2_kernel<<<1, 512>>>(bsum, SCAN_NBLK);
    scan3_kernel<<<zn_grid, 256>>>(off, bsum, cur);
    fill_kernel<<<e_grid, 256>>>(indexes, mask, cur, dstA);
    rowlist_kernel<<<zn_grid, 256>>>(deg, rcnt, rlist);

    // ---- pre-split weights (interleaved) ----
    split_w_kernel<<<sw_grid, 256>>>(in2_W, seg2_W, meta_W, ctr_W, edge_W, ctr2_W,
                                     Whi, Wlo);

    // ---- init: input + seg branches ----
    lin1_kernel<<<lin_grid, 256>>>(nodes, 0, in1_W, in1_b, Ahi, Alo);
    gemm_tc_kernel<<<TC_GRID, TC_THREADS, TC_SMEM>>>(Ahi, Alo, sWp(0), sLp(0), Hbuf, NNODES);
    lin1_kernel<<<lin_grid, 256>>>(nodes, 2, seg1_W, seg1_b, Ahi, Alo);
    gemm_tc_kernel<<<TC_GRID, TC_THREADS, TC_SMEM>>>(Ahi, Alo, sWp(1), sLp(1), res, NNODES);
    gn2_kernel<<<gn_grid, 256>>>(Hbuf, in_g, in_bg, res, seg_g, seg_bg, Ahi, Alo);

    // ---- meta ----
    gemm_tc_kernel<<<TC_GRID, TC_THREADS, TC_SMEM>>>(Ahi, Alo, sWp(2), sLp(2), tmp, NNODES);
    rank4_kernel<<<r4_grid, 256>>>(nodes, meta_W, tmp);
    // res = relu(gn(tmp)); split; zero tmp for layer-0 mp  (feat fp32 not needed yet)
    gn_kernel<<<gn_grid, 256>>>(tmp, meta_g, meta_bg, nullptr, nullptr, res,
                                Ahi, Alo, tmp, 1);

    // ---- 4 message-passing layers ----
    for (int i = 0; i < 4; i++) {
        mp_p_kernel<<<MPP_GRID, MPP_THREADS, MPP_SMEM>>>(Ahi, Alo, Whi, Wlo, i,
                                                         off, deg, dstA, rcnt, rlist,
                                                         tmp, NNODES);
        // split = relu(gn(tmp))  (no fp32 outputs needed)
        gn_kernel<<<gn_grid, 256>>>(tmp, norm_g + i * D, norm_bg + i * D,
                                    nullptr, nullptr, nullptr, Ahi, Alo, nullptr, 1);
        gemm_tc_kernel<<<TC_GRID, TC_THREADS, TC_SMEM>>>(
            Ahi, Alo, sWp(63 + i), sLp(63 + i), tmp, NNODES);
        // feat/res = relu(gn(tmp) + res); last layer writes feat fp32 for output
        gn_kernel<<<gn_grid, 256>>>(tmp, ctr2_g + i * D, ctr2_bg + i * D,
                                    res, (i == 3) ? feat : nullptr,
                                    (i < 3) ? res : nullptr, Ahi, Alo,
                                    (i < 3) ? tmp : nullptr, 1);
    }

    // ---- outputs ----
    int total = NNODES * D + NNODES * 2;
    copy_out_kernel<<<(total + 255) / 256, 256>>>(feat, nodes, out);
}

// round 13
// speedup vs baseline: 1.0590x; 1.0590x over previous
#include <cuda_runtime.h>
#include <cuda_bf16.h>
#include <math.h>
#include <stdint.h>

#define NNODES 100000
#define NEDGES 100000
#define D      128
#define NPAIRS 64
#define NTYPES 14
#define NSLOTS 67   // 0:in2 1:seg2 2:meta 3..6:ctr 7..62:edge 63..66:ctr2

#define SCAN_N   (NTYPES * NNODES)
#define SCAN_BLK 4096
#define SCAN_NBLK ((SCAN_N + SCAN_BLK - 1) / SCAN_BLK)

// ---------------- static device scratch ----------------
__device__ float    g_feat[NNODES * D];
__device__ float    g_res [NNODES * D];
__device__ float    g_tmp [NNODES * D];
__device__ uint32_t g_Ahi [NNODES * NPAIRS];
__device__ uint32_t g_Alo [NNODES * NPAIRS];
__device__ uint32_t g_Whi [NSLOTS * D * NPAIRS];   // pair-interleaved layout
__device__ uint32_t g_Wlo [NSLOTS * D * NPAIRS];
__device__ float    g_H  [NNODES * D];
__device__ int g_deg [SCAN_N];
__device__ int g_off [SCAN_N];
__device__ int g_cur [SCAN_N];
__device__ int g_dst [NTYPES * NEDGES];
__device__ int g_bsum[512];

// ---------------- generic helpers ----------------
__device__ __forceinline__ uint32_t pack_bf16x2(float e0, float e1) {
    uint32_t r;
    asm("cvt.rn.bf16x2.f32 %0, %1, %2;" : "=r"(r) : "f"(e1), "f"(e0));
    return r;
}
__device__ __forceinline__ void split_pair(float x0, float x1,
                                           uint32_t& hi, uint32_t& lo) {
    hi = pack_bf16x2(x0, x1);
    float h0 = __uint_as_float(hi << 16);
    float h1 = __uint_as_float(hi & 0xFFFF0000u);
    lo = pack_bf16x2(x0 - h0, x1 - h1);
}
__device__ __forceinline__ void mma_bf16(float* d, const uint32_t* a, const uint32_t* b) {
    asm volatile(
        "mma.sync.aligned.m16n8k16.row.col.f32.bf16.bf16.f32 "
        "{%0,%1,%2,%3}, {%4,%5,%6,%7}, {%8,%9}, {%0,%1,%2,%3};"
        : "+f"(d[0]), "+f"(d[1]), "+f"(d[2]), "+f"(d[3])
        : "r"(a[0]), "r"(a[1]), "r"(a[2]), "r"(a[3]), "r"(b[0]), "r"(b[1]));
}
__device__ __forceinline__ void red_v4(float* p, float4 v) {
    asm volatile("red.global.add.v4.f32 [%0], {%1, %2, %3, %4};"
                 :: "l"(p), "f"(v.x), "f"(v.y), "f"(v.z), "f"(v.w) : "memory");
}
__device__ __forceinline__ void cp16(uint32_t dst_smem, const void* src) {
    asm volatile("cp.async.ca.shared.global [%0], [%1], 16;" :: "r"(dst_smem), "l"(src));
}
__device__ __forceinline__ uint32_t smem_u32(const void* p) {
    uint32_t a;
    asm("{ .reg .u64 t; cvta.to.shared.u64 t, %1; cvt.u32.u64 %0, t; }" : "=r"(a) : "l"(p));
    return a;
}

// ---------------- CSR build (edge-major, coalesced) ----------------
__global__ void zero_deg_kernel(int* deg) {
    int i = blockIdx.x * blockDim.x + threadIdx.x;
    if (i < SCAN_N) deg[i] = 0;
}
__global__ void deg_kernel(const int* __restrict__ indexes,
                           const int* __restrict__ mask, int* __restrict__ deg) {
    int e = blockIdx.x * blockDim.x + threadIdx.x;
    if (e >= NEDGES) return;
    int4 v[7];
    const int4* row = reinterpret_cast<const int4*>(indexes + e * 28);
    #pragma unroll
    for (int i = 0; i < 7; i++) v[i] = __ldg(row + i);
    const int* vi = reinterpret_cast<const int*>(v);
    #pragma unroll
    for (int t = 0; t < NTYPES; t++) {
        if (e < __ldg(mask + t)) {
            int src = vi[2 * t + 1];
            atomicAdd(&deg[t * NNODES + src], 1);
        }
    }
}
__global__ void scan1_kernel(const int* __restrict__ deg, int* __restrict__ off,
                             int* __restrict__ bsum) {
    __shared__ int warp_tot[8];
    int b = blockIdx.x, tid = threadIdx.x;
    int base = b * SCAN_BLK + tid * 16;
    int v[16];
    int run = 0;
    #pragma unroll
    for (int i = 0; i < 16; i++) {
        int idx = base + i;
        int t = (idx < SCAN_N) ? deg[idx] : 0;
        v[i] = run;
        run += t;
    }
    int lane = tid & 31, w = tid >> 5;
    int x = run;
    #pragma unroll
    for (int o = 1; o < 32; o <<= 1) {
        int y = __shfl_up_sync(0xffffffffu, x, o);
        if (lane >= o) x += y;
    }
    if (lane == 31) warp_tot[w] = x;
    __syncthreads();
    int woff = 0;
    for (int i = 0; i < w; i++) woff += warp_tot[i];
    int excl = x - run + woff;
    #pragma unroll
    for (int i = 0; i < 16; i++)
        if (base + i < SCAN_N) off[base + i] = v[i] + excl;
    if (tid == 255) bsum[b] = excl + run;
}
__global__ void scan2_kernel(int* bsum, int n) {
    __shared__ int sm[512];
    int tid = threadIdx.x;
    int v = (tid < n) ? bsum[tid] : 0;
    sm[tid] = v;
    __syncthreads();
    for (int o = 1; o < 512; o <<= 1) {
        int t = (tid >= o) ? sm[tid - o] : 0;
        __syncthreads();
        sm[tid] += t;
        __syncthreads();
    }
    if (tid < n) bsum[tid] = sm[tid] - v;
}
__global__ void scan3_kernel(int* __restrict__ off, const int* __restrict__ bsum,
                             int* __restrict__ cur) {
    int i = blockIdx.x * blockDim.x + threadIdx.x;
    if (i >= SCAN_N) return;
    int o = off[i] + bsum[i / SCAN_BLK];
    off[i] = o;
    cur[i] = o;
}
__global__ void fill_kernel(const int* __restrict__ indexes,
                            const int* __restrict__ mask,
                            int* __restrict__ cur, int* __restrict__ dstA) {
    int e = blockIdx.x * blockDim.x + threadIdx.x;
    if (e >= NEDGES) return;
    int4 v[7];
    const int4* row = reinterpret_cast<const int4*>(indexes + e * 28);
    #pragma unroll
    for (int i = 0; i < 7; i++) v[i] = __ldg(row + i);
    const int* vi = reinterpret_cast<const int*>(v);
    #pragma unroll
    for (int t = 0; t < NTYPES; t++) {
        if (e < __ldg(mask + t)) {
            int src = vi[2 * t + 1];
            int dst = vi[2 * t];
            int pos = atomicAdd(&cur[t * NNODES + src], 1);
            dstA[pos] = dst;
        }
    }
}

// ---------------- pre-split weights (PAIR-INTERLEAVED gmem layout) -------------
__global__ void split_w_kernel(const float* __restrict__ in2,
                               const float* __restrict__ seg2,
                               const float* __restrict__ meta,
                               const float* __restrict__ ctr,
                               const float* __restrict__ edge,
                               const float* __restrict__ ctr2,
                               uint32_t* __restrict__ Whi,
                               uint32_t* __restrict__ Wlo) {
    int idx = blockIdx.x * blockDim.x + threadIdx.x;
    if (idx >= NSLOTS * D * NPAIRS) return;
    int slot = idx / (D * NPAIRS);
    int r    = idx - slot * (D * NPAIRS);
    int c    = r >> 6;
    int ip   = r & 63;
    int g  = ip >> 3;
    int w  = ip & 7;
    int qk = w >> 1;
    int j  = w & 1;
    int p  = 8 * g + qk + 4 * j;
    int k0 = 2 * p;
    float x0, x1;
    if      (slot == 0) { x0 = in2 [c * D + k0]; x1 = in2 [c * D + k0 + 1]; }
    else if (slot == 1) { x0 = seg2[c * D + k0]; x1 = seg2[c * D + k0 + 1]; }
    else if (slot == 2) { x0 = meta[c * 132 + k0]; x1 = meta[c * 132 + k0 + 1]; }
    else if (slot < 7)  { const float* wm = ctr  + (long)(slot - 3)  * D * D;
                          x0 = wm[c * D + k0]; x1 = wm[c * D + k0 + 1]; }
    else if (slot < 63) { const float* wm = edge + (long)(slot - 7)  * D * D;
                          x0 = wm[c * D + k0]; x1 = wm[c * D + k0 + 1]; }
    else                { const float* wm = ctr2 + (long)(slot - 63) * D * D;
                          x0 = wm[c * D + k0]; x1 = wm[c * D + k0 + 1]; }
    uint32_t hi, lo;
    split_pair(x0, x1, hi, lo);
    Whi[idx] = hi;
    Wlo[idx] = lo;
}

// ---------------- lin1 ----------------
__global__ void lin1_kernel(const float* __restrict__ nodes, int off,
                            const float* __restrict__ W1, const float* __restrict__ b1,
                            uint32_t* __restrict__ Ahi, uint32_t* __restrict__ Alo) {
    int idx = blockIdx.x * blockDim.x + threadIdx.x;
    if (idx >= NNODES * NPAIRS) return;
    int n = idx >> 6;
    int p = idx & 63;
    int j0 = 2 * p;
    float x0 = nodes[n * 8 + off];
    float x1 = nodes[n * 8 + off + 1];
    float v0 = fmaxf(fmaf(x0, W1[j0 * 2],     fmaf(x1, W1[j0 * 2 + 1], b1[j0])),     0.0f);
    float v1 = fmaxf(fmaf(x0, W1[j0 * 2 + 2], fmaf(x1, W1[j0 * 2 + 3], b1[j0 + 1])), 0.0f);
    uint32_t hi, lo;
    split_pair(v0, v1, hi, lo);
    Ahi[idx] = hi;
    Alo[idx] = lo;
}

// ---------------- GEMM (init/meta/ctr2): interleaved W, LDS.64 B-frags --------
#define TC_THREADS 256
#define SW_STR     72
#define TC_SMEM    (2 * D * SW_STR * 4)
#define TC_GRID    296

__global__ void __launch_bounds__(TC_THREADS, 2)
gemm_tc_kernel(const uint32_t* __restrict__ Ahi, const uint32_t* __restrict__ Alo,
               const uint32_t* __restrict__ Whi, const uint32_t* __restrict__ Wlo,
               float* __restrict__ C, int nrows) {
    extern __shared__ uint32_t sm[];
    uint32_t* sWhi = sm;
    uint32_t* sWlo = sm + D * SW_STR;
    int tid = threadIdx.x;

    for (int idx = tid; idx < D * NPAIRS; idx += TC_THREADS) {
        int c = idx >> 6;
        int ip = idx & 63;
        sWhi[c * SW_STR + ip] = Whi[idx];
        sWlo[c * SW_STR + ip] = Wlo[idx];
    }
    __syncthreads();

    int wid  = tid >> 5;
    int lane = tid & 31;
    int rgrp = wid >> 1;
    int cgrp = wid & 1;
    int qr = lane >> 2;
    int qk = lane & 3;

    int ntiles = (nrows + 127) / 128;
    for (int tile = blockIdx.x; tile < ntiles; tile += gridDim.x) {
        int rbase = tile * 128 + rgrp * 32;
        int r00 = rbase + qr;
        int r01 = rbase + qr + 8;
        int r10 = rbase + 16 + qr;
        int r11 = rbase + 16 + qr + 8;
        bool v00 = r00 < nrows, v01 = r01 < nrows;
        bool v10 = r10 < nrows, v11 = r11 < nrows;

        float acc[2][8][4];
        #pragma unroll
        for (int s = 0; s < 2; s++)
            #pragma unroll
            for (int nt = 0; nt < 8; nt++)
                #pragma unroll
                for (int j = 0; j < 4; j++) acc[s][nt][j] = 0.0f;

        #pragma unroll
        for (int kt = 0; kt < 8; kt++) {
            int p0 = kt * 8 + qk;
            int p1 = p0 + 4;
            uint32_t ah0[4], al0[4], ah1[4], al1[4];
            ah0[0] = v00 ? Ahi[(long)r00 * NPAIRS + p0] : 0u;
            ah0[1] = v01 ? Ahi[(long)r01 * NPAIRS + p0] : 0u;
            ah0[2] = v00 ? Ahi[(long)r00 * NPAIRS + p1] : 0u;
            ah0[3] = v01 ? Ahi[(long)r01 * NPAIRS + p1] : 0u;
            al0[0] = v00 ? Alo[(long)r00 * NPAIRS + p0] : 0u;
            al0[1] = v01 ? Alo[(long)r01 * NPAIRS + p0] : 0u;
            al0[2] = v00 ? Alo[(long)r00 * NPAIRS + p1] : 0u;
            al0[3] = v01 ? Alo[(long)r01 * NPAIRS + p1] : 0u;
            ah1[0] = v10 ? Ahi[(long)r10 * NPAIRS + p0] : 0u;
            ah1[1] = v11 ? Ahi[(long)r11 * NPAIRS + p0] : 0u;
            ah1[2] = v10 ? Ahi[(long)r10 * NPAIRS + p1] : 0u;
            ah1[3] = v11 ? Ahi[(long)r11 * NPAIRS + p1] : 0u;
            al1[0] = v10 ? Alo[(long)r10 * NPAIRS + p0] : 0u;
            al1[1] = v11 ? Alo[(long)r11 * NPAIRS + p0] : 0u;
            al1[2] = v10 ? Alo[(long)r10 * NPAIRS + p1] : 0u;
            al1[3] = v11 ? Alo[(long)r11 * NPAIRS + p1] : 0u;

            #pragma unroll
            for (int nt = 0; nt < 8; nt++) {
                int n = cgrp * 64 + nt * 8 + qr;
                int o = n * SW_STR + kt * 8 + 2 * qk;
                uint2 BH = *reinterpret_cast<const uint2*>(&sWhi[o]);
                uint2 BL = *reinterpret_cast<const uint2*>(&sWlo[o]);
                uint32_t bh[2] = { BH.x, BH.y };
                uint32_t bl[2] = { BL.x, BL.y };
                mma_bf16(acc[0][nt], ah0, bh);
                mma_bf16(acc[0][nt], al0, bh);
                mma_bf16(acc[0][nt], ah0, bl);
                mma_bf16(acc[1][nt], ah1, bh);
                mma_bf16(acc[1][nt], al1, bh);
                mma_bf16(acc[1][nt], ah1, bl);
            }
        }

        #pragma unroll
        for (int nt = 0; nt < 8; nt++) {
            int col = cgrp * 64 + nt * 8 + 2 * qk;
            if (v00) *reinterpret_cast<float2*>(C + (long)r00 * D + col) =
                         make_float2(acc[0][nt][0], acc[0][nt][1]);
            if (v01) *reinterpret_cast<float2*>(C + (long)r01 * D + col) =
                         make_float2(acc[0][nt][2], acc[0][nt][3]);
            if (v10) *reinterpret_cast<float2*>(C + (long)r10 * D + col) =
                         make_float2(acc[1][nt][0], acc[1][nt][1]);
            if (v11) *reinterpret_cast<float2*>(C + (long)r11 * D + col) =
                         make_float2(acc[1][nt][2], acc[1][nt][3]);
        }
    }
}

// ---------------- persistent fused message-passing layer (DENSE tiles) --------
// grid=148, 512 thr (16 warps). Slots OUTER, tiles INNER (block tile = 256 rows).
// Warp = 32 rows (2 strips) x 64 cols; B-frags reused across strips.
#define MPP_THREADS 512
#define MPP_GRID    148
#define WP_STR      72
#define W_TILE      (D * WP_STR)
#define STG_STR     72
#define MPP_SMEM    ((4 * W_TILE + 16 * 16 * STG_STR) * 4)

__global__ void __launch_bounds__(MPP_THREADS, 1)
mp_p_kernel(const uint32_t* __restrict__ Ahi, const uint32_t* __restrict__ Alo,
            const uint32_t* __restrict__ Whi, const uint32_t* __restrict__ Wlo,
            int layer,
            const int* __restrict__ off, const int* __restrict__ deg,
            const int* __restrict__ dstA,
            float* __restrict__ tmp, int nrows) {
    extern __shared__ uint32_t sm[];
    float* stage = reinterpret_cast<float*>(sm + 4 * W_TILE);
    uint32_t sbase = smem_u32(sm);

    int tid  = threadIdx.x;
    int wid  = tid >> 5;
    int lane = tid & 31;
    int rg = wid >> 1;
    int ch = wid & 1;
    int qr = lane >> 2;
    int qk = lane & 3;

    auto slot_of = [&](int s) {
        return (s == 0) ? (3 + layer) : (7 + layer * NTYPES + s - 1);
    };
    auto cp_w = [&](int s, int b) {
        const uint32_t* wh = Whi + (long)slot_of(s) * D * NPAIRS;
        const uint32_t* wl = Wlo + (long)slot_of(s) * D * NPAIRS;
        uint32_t bh = sbase + (uint32_t)(2 * b)     * W_TILE * 4u;
        uint32_t bl = sbase + (uint32_t)(2 * b + 1) * W_TILE * 4u;
        for (int i = tid * 4; i < D * NPAIRS; i += MPP_THREADS * 4) {
            int c = i >> 6, ip = i & 63;
            uint32_t o = (uint32_t)(c * WP_STR + ip) * 4u;
            cp16(bh + o, wh + i);
            cp16(bl + o, wl + i);
        }
        asm volatile("cp.async.commit_group;" ::: "memory");
    };

    cp_w(0, 0);

    int ntiles = (nrows + 255) / 256;
    for (int s = 0; s < 15; s++) {
        asm volatile("cp.async.wait_group 0;" ::: "memory");
        __syncthreads();
        if (s < 14) cp_w(s + 1, (s + 1) & 1);

        const uint32_t* sWhi = sm + (size_t)(2 * (s & 1))     * W_TILE;
        const uint32_t* sWlo = sm + (size_t)(2 * (s & 1) + 1) * W_TILE;
        int t = s - 1;

        for (int tile = blockIdx.x; tile < ntiles; tile += MPP_GRID) {
            int rb = tile * 256 + rg * 32;
            int r00 = rb + qr;
            int r01 = rb + qr + 8;
            int r10 = rb + 16 + qr;
            int r11 = rb + 16 + qr + 8;
            bool v00 = r00 < nrows, v01 = r01 < nrows;
            bool v10 = r10 < nrows, v11 = r11 < nrows;

            float acc[2][8][4];
            #pragma unroll
            for (int s2 = 0; s2 < 2; s2++)
                #pragma unroll
                for (int nt = 0; nt < 8; nt++)
                    #pragma unroll
                    for (int j = 0; j < 4; j++) acc[s2][nt][j] = 0.0f;

            #pragma unroll 2
            for (int kt = 0; kt < 8; kt++) {
                int p0 = kt * 8 + qk;
                int p1 = p0 + 4;
                uint32_t ah0[4], al0[4], ah1[4], al1[4];
                ah0[0] = v00 ? Ahi[(long)r00 * NPAIRS + p0] : 0u;
                ah0[1] = v01 ? Ahi[(long)r01 * NPAIRS + p0] : 0u;
                ah0[2] = v00 ? Ahi[(long)r00 * NPAIRS + p1] : 0u;
                ah0[3] = v01 ? Ahi[(long)r01 * NPAIRS + p1] : 0u;
                al0[0] = v00 ? Alo[(long)r00 * NPAIRS + p0] : 0u;
                al0[1] = v01 ? Alo[(long)r01 * NPAIRS + p0] : 0u;
                al0[2] = v00 ? Alo[(long)r00 * NPAIRS + p1] : 0u;
                al0[3] = v01 ? Alo[(long)r01 * NPAIRS + p1] : 0u;
                ah1[0] = v10 ? Ahi[(long)r10 * NPAIRS + p0] : 0u;
                ah1[1] = v11 ? Ahi[(long)r11 * NPAIRS + p0] : 0u;
                ah1[2] = v10 ? Ahi[(long)r10 * NPAIRS + p1] : 0u;
                ah1[3] = v11 ? Ahi[(long)r11 * NPAIRS + p1] : 0u;
                al1[0] = v10 ? Alo[(long)r10 * NPAIRS + p0] : 0u;
                al1[1] = v11 ? Alo[(long)r11 * NPAIRS + p0] : 0u;
                al1[2] = v10 ? Alo[(long)r10 * NPAIRS + p1] : 0u;
                al1[3] = v11 ? Alo[(long)r11 * NPAIRS + p1] : 0u;

                #pragma unroll
                for (int nt = 0; nt < 8; nt++) {
                    int n = ch * 64 + nt * 8 + qr;
                    int o = n * WP_STR + kt * 8 + 2 * qk;
                    uint2 BH = *reinterpret_cast<const uint2*>(&sWhi[o]);
                    uint2 BL = *reinterpret_cast<const uint2*>(&sWlo[o]);
                    uint32_t bh[2] = { BH.x, BH.y };
                    uint32_t bl[2] = { BL.x, BL.y };
                    mma_bf16(acc[0][nt], ah0, bh);
                    mma_bf16(acc[0][nt], al0, bh);
                    mma_bf16(acc[0][nt], ah0, bl);
                    mma_bf16(acc[1][nt], ah1, bh);
                    mma_bf16(acc[1][nt], al1, bh);
                    mma_bf16(acc[1][nt], ah1, bl);
                }
            }

            float* st = stage + wid * (16 * STG_STR);
            #pragma unroll
            for (int s2 = 0; s2 < 2; s2++) {
                #pragma unroll
                for (int nt = 0; nt < 8; nt++) {
                    int c2 = nt * 8 + 2 * qk;
                    *reinterpret_cast<float2*>(&st[qr * STG_STR + c2]) =
                        make_float2(acc[s2][nt][0], acc[s2][nt][1]);
                    *reinterpret_cast<float2*>(&st[(qr + 8) * STG_STR + c2]) =
                        make_float2(acc[s2][nt][2], acc[s2][nt][3]);
                }
                __syncwarp();

                int srow = rb + s2 * 16;
                int colg = ch * 64 + (lane & 15) * 4;
                #pragma unroll
                for (int rr = 0; rr < 16; rr += 2) {
                    int lr  = rr + (lane >> 4);
                    int row = srow + lr;
                    float4 v = *reinterpret_cast<float4*>(
                        &st[lr * STG_STR + (lane & 15) * 4]);
                    if (row < nrows) {
                        if (s == 0) {
                            red_v4(tmp + (long)row * D + colg, v);
                        } else {
                            long key = (long)t * NNODES + row;
                            int o0 = __ldg(off + key);
                            int dg = __ldg(deg + key);
                            for (int e = 0; e < dg; e++) {
                                int d = __ldg(dstA + o0 + e);
                                red_v4(tmp + (long)d * D + colg, v);
                            }
                        }
                    }
                }
                __syncwarp();
            }
        }
    }
}

// ---------------- GroupNorm helpers ----------------
__device__ __forceinline__ float warp_sum(float v) {
    #pragma unroll
    for (int o = 16; o > 0; o >>= 1) v += __shfl_xor_sync(0xffffffffu, v, o);
    return v;
}
__device__ __forceinline__ void store_split4(uint32_t* Ahi, uint32_t* Alo,
                                             int row, int lane, float4 y) {
    uint32_t h0, l0, h1, l1;
    split_pair(y.x, y.y, h0, l0);
    split_pair(y.z, y.w, h1, l1);
    *reinterpret_cast<uint2*>(Ahi + (long)row * NPAIRS + lane * 2) = make_uint2(h0, h1);
    *reinterpret_cast<uint2*>(Alo + (long)row * NPAIRS + lane * 2) = make_uint2(l0, l1);
}

__global__ void gn_kernel(const float* __restrict__ in,
                          const float* __restrict__ g, const float* __restrict__ b,
                          const float* __restrict__ resid,
                          float* __restrict__ out1, float* __restrict__ out2,
                          uint32_t* __restrict__ Ahi, uint32_t* __restrict__ Alo,
                          float* __restrict__ zbuf,
                          int do_relu) {
    int warp = (blockIdx.x * blockDim.x + threadIdx.x) >> 5;
    int lane = threadIdx.x & 31;
    if (warp >= NNODES) return;
    const float4 x = *reinterpret_cast<const float4*>(in + (long)warp * D + lane * 4);
    float s  = x.x + x.y + x.z + x.w;
    float ss = x.x * x.x + x.y * x.y + x.z * x.z + x.w * x.w;
    s  = warp_sum(s);
    ss = warp_sum(ss);
    float m   = s * (1.0f / 128.0f);
    float var = ss * (1.0f / 128.0f) - m * m;
    float inv = rsqrtf(var + 1e-5f);
    float4 gg = *reinterpret_cast<const float4*>(g + lane * 4);
    float4 bb = *reinterpret_cast<const float4*>(b + lane * 4);
    float4 y;
    y.x = fmaf((x.x - m) * inv, gg.x, bb.x);
    y.y = fmaf((x.y - m) * inv, gg.y, bb.y);
    y.z = fmaf((x.z - m) * inv, gg.z, bb.z);
    y.w = fmaf((x.w - m) * inv, gg.w, bb.w);
    if (resid) {
        float4 r = *reinterpret_cast<const float4*>(resid + (long)warp * D + lane * 4);
        y.x += r.x; y.y += r.y; y.z += r.z; y.w += r.w;
    }
    if (do_relu) {
        y.x = fmaxf(y.x, 0.0f); y.y = fmaxf(y.y, 0.0f);
        y.z = fmaxf(y.z, 0.0f); y.w = fmaxf(y.w, 0.0f);
    }
    if (out1)
        *reinterpret_cast<float4*>(out1 + (long)warp * D + lane * 4) = y;
    if (out2)
        *reinterpret_cast<float4*>(out2 + (long)warp * D + lane * 4) = y;
    if (Ahi) store_split4(Ahi, Alo, warp, lane, y);
    if (zbuf)
        *reinterpret_cast<float4*>(zbuf + (long)warp * D + lane * 4) =
            make_float4(0.f, 0.f, 0.f, 0.f);
}

__global__ void gn2_kernel(const float* __restrict__ inA,
                           const float* __restrict__ gA, const float* __restrict__ bA,
                           const float* __restrict__ inB,
                           const float* __restrict__ gB, const float* __restrict__ bB,
                           uint32_t* __restrict__ Ahi, uint32_t* __restrict__ Alo) {
    int warp = (blockIdx.x * blockDim.x + threadIdx.x) >> 5;
    int lane = threadIdx.x & 31;
    if (warp >= NNODES) return;
    const float4 xa = *reinterpret_cast<const float4*>(inA + (long)warp * D + lane * 4);
    const float4 xb = *reinterpret_cast<const float4*>(inB + (long)warp * D + lane * 4);
    float sa  = xa.x + xa.y + xa.z + xa.w;
    float ssa = xa.x * xa.x + xa.y * xa.y + xa.z * xa.z + xa.w * xa.w;
    float sb  = xb.x + xb.y + xb.z + xb.w;
    float ssb = xb.x * xb.x + xb.y * xb.y + xb.z * xb.z + xb.w * xb.w;
    sa = warp_sum(sa); ssa = warp_sum(ssa);
    sb = warp_sum(sb); ssb = warp_sum(ssb);
    float ma = sa * (1.0f / 128.0f);
    float mb = sb * (1.0f / 128.0f);
    float ia = rsqrtf(ssa * (1.0f / 128.0f) - ma * ma + 1e-5f);
    float ib = rsqrtf(ssb * (1.0f / 128.0f) - mb * mb + 1e-5f);
    float4 ga4 = *reinterpret_cast<const float4*>(gA + lane * 4);
    float4 ba4 = *reinterpret_cast<const float4*>(bA + lane * 4);
    float4 gb4 = *reinterpret_cast<const float4*>(gB + lane * 4);
    float4 bb4 = *reinterpret_cast<const float4*>(bB + lane * 4);
    float4 y;
    y.x = fmaf((xa.x - ma) * ia, ga4.x, ba4.x) + fmaf((xb.x - mb) * ib, gb4.x, bb4.x);
    y.y = fmaf((xa.y - ma) * ia, ga4.y, ba4.y) + fmaf((xb.y - mb) * ib, gb4.y, bb4.y);
    y.z = fmaf((xa.z - ma) * ia, ga4.z, ba4.z) + fmaf((xb.z - mb) * ib, gb4.z, bb4.z);
    y.w = fmaf((xa.w - ma) * ia, ga4.w, ba4.w) + fmaf((xb.w - mb) * ib, gb4.w, bb4.w);
    y.x = fmaxf(y.x, 0.0f); y.y = fmaxf(y.y, 0.0f);
    y.z = fmaxf(y.z, 0.0f); y.w = fmaxf(y.w, 0.0f);
    store_split4(Ahi, Alo, warp, lane, y);
}

// ---------------- rank-4 update ----------------
__global__ void rank4_kernel(const float* __restrict__ nodes,
                             const float* __restrict__ metaW,
                             float* __restrict__ out) {
    int idx = blockIdx.x * blockDim.x + threadIdx.x;
    if (idx >= NNODES * D) return;
    int n = idx >> 7;
    int c = idx & 127;
    const float* wr = metaW + c * 132 + 128;
    const float* nd = nodes + n * 8 + 4;
    float s = fmaf(nd[0], wr[0], fmaf(nd[1], wr[1], fmaf(nd[2], wr[2], nd[3] * wr[3])));
    out[idx] += s;
}

// ---------------- final output ----------------
__global__ void copy_out_kernel(const float* __restrict__ feat,
                                const float* __restrict__ nodes,
                                float* __restrict__ out) {
    int idx = blockIdx.x * blockDim.x + threadIdx.x;
    const int F = NNODES * D;
    if (idx < F) {
        out[idx] = feat[idx];
    } else if (idx < F + NNODES * 2) {
        int j = idx - F;
        int n = j >> 1;
        int c = j & 1;
        out[idx] = nodes[n * 8 + c];
    }
}

// ---------------- host launcher ----------------
extern "C" void kernel_launch(void* const* d_in, const int* in_sizes, int n_in,
                              void* d_out, int out_size) {
    const float* nodes   = (const float*)d_in[0];
    const int*   indexes = (const int*)  d_in[1];
    const int*   mask    = (const int*)  d_in[2];
    const float* in1_W   = (const float*)d_in[3];
    const float* in1_b   = (const float*)d_in[4];
    const float* in2_W   = (const float*)d_in[5];
    const float* in_g    = (const float*)d_in[6];
    const float* in_bg   = (const float*)d_in[7];
    const float* seg1_W  = (const float*)d_in[8];
    const float* seg1_b  = (const float*)d_in[9];
    const float* seg2_W  = (const float*)d_in[10];
    const float* seg_g   = (const float*)d_in[11];
    const float* seg_bg  = (const float*)d_in[12];
    const float* meta_W  = (const float*)d_in[13];
    const float* meta_g  = (const float*)d_in[14];
    const float* meta_bg = (const float*)d_in[15];
    const float* ctr_W   = (const float*)d_in[16];
    const float* edge_W  = (const float*)d_in[17];
    const float* norm_g  = (const float*)d_in[18];
    const float* norm_bg = (const float*)d_in[19];
    const float* ctr2_W  = (const float*)d_in[20];
    const float* ctr2_g  = (const float*)d_in[21];
    const float* ctr2_bg = (const float*)d_in[22];
    float* out = (float*)d_out;

    float *feat, *res, *tmp;
    uint32_t *Whi, *Wlo, *Ahi, *Alo;
    int *deg, *off, *cur, *dstA, *bsum;
    cudaGetSymbolAddress((void**)&feat, g_feat);
    cudaGetSymbolAddress((void**)&res,  g_res);
    cudaGetSymbolAddress((void**)&tmp,  g_tmp);
    cudaGetSymbolAddress((void**)&Whi,  g_Whi);
    cudaGetSymbolAddress((void**)&Wlo,  g_Wlo);
    cudaGetSymbolAddress((void**)&Ahi,  g_Ahi);
    cudaGetSymbolAddress((void**)&Alo,  g_Alo);
    cudaGetSymbolAddress((void**)&deg,  g_deg);
    cudaGetSymbolAddress((void**)&off,  g_off);
    cudaGetSymbolAddress((void**)&cur,  g_cur);
    cudaGetSymbolAddress((void**)&dstA, g_dst);
    cudaGetSymbolAddress((void**)&bsum, g_bsum);
    float* Hbuf;
    cudaGetSymbolAddress((void**)&Hbuf, g_H);

    cudaFuncSetAttribute(gemm_tc_kernel,
                         cudaFuncAttributeMaxDynamicSharedMemorySize, TC_SMEM);
    cudaFuncSetAttribute(mp_p_kernel,
                         cudaFuncAttributeMaxDynamicSharedMemorySize, MPP_SMEM);

    const int lin_grid = (NNODES * NPAIRS + 255) / 256;
    const int gn_grid  = (NNODES * 32 + 255) / 256;
    const int sw_grid  = (NSLOTS * D * NPAIRS + 255) / 256;
    const int r4_grid  = (NNODES * D + 255) / 256;
    const int e_grid   = (NEDGES + 255) / 256;
    const int zn_grid  = (SCAN_N + 255) / 256;

    auto sWp = [&](int s) { return Whi + (long)s * D * NPAIRS; };
    auto sLp = [&](int s) { return Wlo + (long)s * D * NPAIRS; };

    // ---- CSR build (edge-major) ----
    zero_deg_kernel<<<zn_grid, 256>>>(deg);
    deg_kernel<<<e_grid, 256>>>(indexes, mask, deg);
    scan1_kernel<<<SCAN_NBLK, 256>>>(deg, off, bsum);
    scan2_kernel<<<1, 512>>>(bsum, SCAN_NBLK);
    scan3_kernel<<<zn_grid, 256>>>(off, bsum, cur);
    fill_kernel<<<e_grid, 256>>>(indexes, mask, cur, dstA);

    // ---- pre-split weights (interleaved) ----
    split_w_kernel<<<sw_grid, 256>>>(in2_W, seg2_W, meta_W, ctr_W, edge_W, ctr2_W,
                                     Whi, Wlo);

    // ---- init: input + seg branches ----
    lin1_kernel<<<lin_grid, 256>>>(nodes, 0, in1_W, in1_b, Ahi, Alo);
    gemm_tc_kernel<<<TC_GRID, TC_THREADS, TC_SMEM>>>(Ahi, Alo, sWp(0), sLp(0), Hbuf, NNODES);
    lin1_kernel<<<lin_grid, 256>>>(nodes, 2, seg1_W, seg1_b, Ahi, Alo);
    gemm_tc_kernel<<<TC_GRID, TC_THREADS, TC_SMEM>>>(Ahi, Alo, sWp(1), sLp(1), res, NNODES);
    gn2_kernel<<<gn_grid, 256>>>(Hbuf, in_g, in_bg, res, seg_g, seg_bg, Ahi, Alo);

    // ---- meta ----
    gemm_tc_kernel<<<TC_GRID, TC_THREADS, TC_SMEM>>>(Ahi, Alo, sWp(2), sLp(2), tmp, NNODES);
    rank4_kernel<<<r4_grid, 256>>>(nodes, meta_W, tmp);
    // res = relu(gn(tmp)); split; zero tmp for layer-0 mp  (feat fp32 not needed yet)
    gn_kernel<<<gn_grid, 256>>>(tmp, meta_g, meta_bg, nullptr, nullptr, res,
                                Ahi, Alo, tmp, 1);

    // ---- 4 message-passing layers ----
    for (int i = 0; i < 4; i++) {
        mp_p_kernel<<<MPP_GRID, MPP_THREADS, MPP_SMEM>>>(Ahi, Alo, Whi, Wlo, i,
                                                         off, deg, dstA, tmp, NNODES);
        // split = relu(gn(tmp))  (no fp32 outputs needed)
        gn_kernel<<<gn_grid, 256>>>(tmp, norm_g + i * D, norm_bg + i * D,
                                    nullptr, nullptr, nullptr, Ahi, Alo, nullptr, 1);
        gemm_tc_kernel<<<TC_GRID, TC_THREADS, TC_SMEM>>>(
            Ahi, Alo, sWp(63 + i), sLp(63 + i), tmp, NNODES);
        // feat/res = relu(gn(tmp) + res); last layer writes feat fp32 for output
        gn_kernel<<<gn_grid, 256>>>(tmp, ctr2_g + i * D, ctr2_bg + i * D,
                                    res, (i == 3) ? feat : nullptr,
                                    (i < 3) ? res : nullptr, Ahi, Alo,
                                    (i < 3) ? tmp : nullptr, 1);
    }

    // ---- outputs ----
    int total = NNODES * D + NNODES * 2;
    copy_out_kernel<<<(total + 255) / 256, 256>>>(feat, nodes, out);
}

// round 14
// speedup vs baseline: 1.2284x; 1.1601x over previous
#include <cuda_runtime.h>
#include <cuda_bf16.h>
#include <math.h>
#include <stdint.h>

#define NNODES 100000
#define NEDGES 100000
#define D      128
#define NPAIRS 64
#define NTYPES 14
#define NSLOTS 67   // 0:in2 1:seg2 2:meta 3..6:ctr 7..62:edge 63..66:ctr2

#define SCAN_N   (NTYPES * NNODES)
#define SCAN_BLK 4096
#define SCAN_NBLK ((SCAN_N + SCAN_BLK - 1) / SCAN_BLK)

// ---------------- static device scratch ----------------
__device__ float    g_feat[NNODES * D];
__device__ float    g_res [NNODES * D];
__device__ float    g_tmp [NNODES * D];
__device__ uint32_t g_Ahi [NNODES * NPAIRS];
__device__ uint32_t g_Alo [NNODES * NPAIRS];
__device__ uint32_t g_Whi [NSLOTS * D * NPAIRS];   // pair-interleaved layout
__device__ uint32_t g_Wlo [NSLOTS * D * NPAIRS];
__device__ float    g_H  [NNODES * D];
__device__ int g_deg [SCAN_N];
__device__ int g_off [SCAN_N];
__device__ int g_cur [SCAN_N];
__device__ int g_dst [NTYPES * NEDGES];
__device__ int g_bsum [512];
__device__ int g_foff [SCAN_N];              // scan of (deg>0) flags
__device__ int g_fbsum[512];
__device__ int g_rstart[NTYPES + 1];         // per-type start into rlist
__device__ int g_rlist[SCAN_N];              // SORTED compacted src lists

// ---------------- generic helpers ----------------
__device__ __forceinline__ uint32_t pack_bf16x2(float e0, float e1) {
    uint32_t r;
    asm("cvt.rn.bf16x2.f32 %0, %1, %2;" : "=r"(r) : "f"(e1), "f"(e0));
    return r;
}
__device__ __forceinline__ void split_pair(float x0, float x1,
                                           uint32_t& hi, uint32_t& lo) {
    hi = pack_bf16x2(x0, x1);
    float h0 = __uint_as_float(hi << 16);
    float h1 = __uint_as_float(hi & 0xFFFF0000u);
    lo = pack_bf16x2(x0 - h0, x1 - h1);
}
__device__ __forceinline__ void mma_bf16(float* d, const uint32_t* a, const uint32_t* b) {
    asm volatile(
        "mma.sync.aligned.m16n8k16.row.col.f32.bf16.bf16.f32 "
        "{%0,%1,%2,%3}, {%4,%5,%6,%7}, {%8,%9}, {%0,%1,%2,%3};"
        : "+f"(d[0]), "+f"(d[1]), "+f"(d[2]), "+f"(d[3])
        : "r"(a[0]), "r"(a[1]), "r"(a[2]), "r"(a[3]), "r"(b[0]), "r"(b[1]));
}
__device__ __forceinline__ void red_v4(float* p, float4 v) {
    asm volatile("red.global.add.v4.f32 [%0], {%1, %2, %3, %4};"
                 :: "l"(p), "f"(v.x), "f"(v.y), "f"(v.z), "f"(v.w) : "memory");
}
__device__ __forceinline__ void cp16(uint32_t dst_smem, const void* src) {
    asm volatile("cp.async.ca.shared.global [%0], [%1], 16;" :: "r"(dst_smem), "l"(src));
}
__device__ __forceinline__ uint32_t smem_u32(const void* p) {
    uint32_t a;
    asm("{ .reg .u64 t; cvta.to.shared.u64 t, %1; cvt.u32.u64 %0, t; }" : "=r"(a) : "l"(p));
    return a;
}

// ---------------- CSR build (edge-major, coalesced) ----------------
__global__ void zero_deg_kernel(int* deg) {
    int i = blockIdx.x * blockDim.x + threadIdx.x;
    if (i < SCAN_N) deg[i] = 0;
}
__global__ void deg_kernel(const int* __restrict__ indexes,
                           const int* __restrict__ mask, int* __restrict__ deg) {
    int e = blockIdx.x * blockDim.x + threadIdx.x;
    if (e >= NEDGES) return;
    int4 v[7];
    const int4* row = reinterpret_cast<const int4*>(indexes + e * 28);
    #pragma unroll
    for (int i = 0; i < 7; i++) v[i] = __ldg(row + i);
    const int* vi = reinterpret_cast<const int*>(v);
    #pragma unroll
    for (int t = 0; t < NTYPES; t++) {
        if (e < __ldg(mask + t)) {
            int src = vi[2 * t + 1];
            atomicAdd(&deg[t * NNODES + src], 1);
        }
    }
}
// generic block scan: mode 0 -> scan deg values; mode 1 -> scan (deg>0) flags
__global__ void scan1_kernel(const int* __restrict__ deg, int* __restrict__ off,
                             int* __restrict__ bsum, int mode) {
    __shared__ int warp_tot[8];
    int b = blockIdx.x, tid = threadIdx.x;
    int base = b * SCAN_BLK + tid * 16;
    int v[16];
    int run = 0;
    #pragma unroll
    for (int i = 0; i < 16; i++) {
        int idx = base + i;
        int t = (idx < SCAN_N) ? deg[idx] : 0;
        if (mode) t = (t > 0) ? 1 : 0;
        v[i] = run;
        run += t;
    }
    int lane = tid & 31, w = tid >> 5;
    int x = run;
    #pragma unroll
    for (int o = 1; o < 32; o <<= 1) {
        int y = __shfl_up_sync(0xffffffffu, x, o);
        if (lane >= o) x += y;
    }
    if (lane == 31) warp_tot[w] = x;
    __syncthreads();
    int woff = 0;
    for (int i = 0; i < w; i++) woff += warp_tot[i];
    int excl = x - run + woff;
    #pragma unroll
    for (int i = 0; i < 16; i++)
        if (base + i < SCAN_N) off[base + i] = v[i] + excl;
    if (tid == 255) bsum[b] = excl + run;
}
__global__ void scan2_kernel(int* bsum, int n) {
    __shared__ int sm[512];
    int tid = threadIdx.x;
    int v = (tid < n) ? bsum[tid] : 0;
    sm[tid] = v;
    __syncthreads();
    for (int o = 1; o < 512; o <<= 1) {
        int t = (tid >= o) ? sm[tid - o] : 0;
        __syncthreads();
        sm[tid] += t;
        __syncthreads();
    }
    if (tid < n) bsum[tid] = sm[tid] - v;
}
__global__ void scan3_kernel(int* __restrict__ off, const int* __restrict__ bsum,
                             int* __restrict__ cur) {
    int i = blockIdx.x * blockDim.x + threadIdx.x;
    if (i >= SCAN_N) return;
    int o = off[i] + bsum[i / SCAN_BLK];
    off[i] = o;
    cur[i] = o;
}
// finalize flag scan: emit SORTED rlist + per-type starts
__global__ void scan3f_kernel(const int* __restrict__ deg,
                              const int* __restrict__ foff,
                              const int* __restrict__ fbsum,
                              int* __restrict__ rlist, int* __restrict__ rstart) {
    int i = blockIdx.x * blockDim.x + threadIdx.x;
    if (i >= SCAN_N) return;
    int fo = foff[i] + fbsum[i / SCAN_BLK];
    int t   = i / NNODES;
    int src = i - t * NNODES;
    int live = (deg[i] > 0) ? 1 : 0;
    if (live) rlist[fo] = src;
    if (src == 0) rstart[t] = fo;
    if (i == SCAN_N - 1) rstart[NTYPES] = fo + live;
}
__global__ void fill_kernel(const int* __restrict__ indexes,
                            const int* __restrict__ mask,
                            int* __restrict__ cur, int* __restrict__ dstA) {
    int e = blockIdx.x * blockDim.x + threadIdx.x;
    if (e >= NEDGES) return;
    int4 v[7];
    const int4* row = reinterpret_cast<const int4*>(indexes + e * 28);
    #pragma unroll
    for (int i = 0; i < 7; i++) v[i] = __ldg(row + i);
    const int* vi = reinterpret_cast<const int*>(v);
    #pragma unroll
    for (int t = 0; t < NTYPES; t++) {
        if (e < __ldg(mask + t)) {
            int src = vi[2 * t + 1];
            int dst = vi[2 * t];
            int pos = atomicAdd(&cur[t * NNODES + src], 1);
            dstA[pos] = dst;
        }
    }
}

// ---------------- pre-split weights (PAIR-INTERLEAVED gmem layout) -------------
__global__ void split_w_kernel(const float* __restrict__ in2,
                               const float* __restrict__ seg2,
                               const float* __restrict__ meta,
                               const float* __restrict__ ctr,
                               const float* __restrict__ edge,
                               const float* __restrict__ ctr2,
                               uint32_t* __restrict__ Whi,
                               uint32_t* __restrict__ Wlo) {
    int idx = blockIdx.x * blockDim.x + threadIdx.x;
    if (idx >= NSLOTS * D * NPAIRS) return;
    int slot = idx / (D * NPAIRS);
    int r    = idx - slot * (D * NPAIRS);
    int c    = r >> 6;
    int ip   = r & 63;
    int g  = ip >> 3;
    int w  = ip & 7;
    int qk = w >> 1;
    int j  = w & 1;
    int p  = 8 * g + qk + 4 * j;
    int k0 = 2 * p;
    float x0, x1;
    if      (slot == 0) { x0 = in2 [c * D + k0]; x1 = in2 [c * D + k0 + 1]; }
    else if (slot == 1) { x0 = seg2[c * D + k0]; x1 = seg2[c * D + k0 + 1]; }
    else if (slot == 2) { x0 = meta[c * 132 + k0]; x1 = meta[c * 132 + k0 + 1]; }
    else if (slot < 7)  { const float* wm = ctr  + (long)(slot - 3)  * D * D;
                          x0 = wm[c * D + k0]; x1 = wm[c * D + k0 + 1]; }
    else if (slot < 63) { const float* wm = edge + (long)(slot - 7)  * D * D;
                          x0 = wm[c * D + k0]; x1 = wm[c * D + k0 + 1]; }
    else                { const float* wm = ctr2 + (long)(slot - 63) * D * D;
                          x0 = wm[c * D + k0]; x1 = wm[c * D + k0 + 1]; }
    uint32_t hi, lo;
    split_pair(x0, x1, hi, lo);
    Whi[idx] = hi;
    Wlo[idx] = lo;
}

// ---------------- lin1 ----------------
__global__ void lin1_kernel(const float* __restrict__ nodes, int off,
                            const float* __restrict__ W1, const float* __restrict__ b1,
                            uint32_t* __restrict__ Ahi, uint32_t* __restrict__ Alo) {
    int idx = blockIdx.x * blockDim.x + threadIdx.x;
    if (idx >= NNODES * NPAIRS) return;
    int n = idx >> 6;
    int p = idx & 63;
    int j0 = 2 * p;
    float x0 = nodes[n * 8 + off];
    float x1 = nodes[n * 8 + off + 1];
    float v0 = fmaxf(fmaf(x0, W1[j0 * 2],     fmaf(x1, W1[j0 * 2 + 1], b1[j0])),     0.0f);
    float v1 = fmaxf(fmaf(x0, W1[j0 * 2 + 2], fmaf(x1, W1[j0 * 2 + 3], b1[j0 + 1])), 0.0f);
    uint32_t hi, lo;
    split_pair(v0, v1, hi, lo);
    Ahi[idx] = hi;
    Alo[idx] = lo;
}

// ---------------- GEMM (init/meta/ctr2): interleaved W, LDS.64 B-frags --------
#define TC_THREADS 256
#define SW_STR     72
#define TC_SMEM    (2 * D * SW_STR * 4)
#define TC_GRID    296

__global__ void __launch_bounds__(TC_THREADS, 2)
gemm_tc_kernel(const uint32_t* __restrict__ Ahi, const uint32_t* __restrict__ Alo,
               const uint32_t* __restrict__ Whi, const uint32_t* __restrict__ Wlo,
               float* __restrict__ C, int nrows) {
    extern __shared__ uint32_t sm[];
    uint32_t* sWhi = sm;
    uint32_t* sWlo = sm + D * SW_STR;
    int tid = threadIdx.x;

    for (int idx = tid; idx < D * NPAIRS; idx += TC_THREADS) {
        int c = idx >> 6;
        int ip = idx & 63;
        sWhi[c * SW_STR + ip] = Whi[idx];
        sWlo[c * SW_STR + ip] = Wlo[idx];
    }
    __syncthreads();

    int wid  = tid >> 5;
    int lane = tid & 31;
    int rgrp = wid >> 1;
    int cgrp = wid & 1;
    int qr = lane >> 2;
    int qk = lane & 3;

    int ntiles = (nrows + 127) / 128;
    for (int tile = blockIdx.x; tile < ntiles; tile += gridDim.x) {
        int rbase = tile * 128 + rgrp * 32;
        int r00 = rbase + qr;
        int r01 = rbase + qr + 8;
        int r10 = rbase + 16 + qr;
        int r11 = rbase + 16 + qr + 8;
        bool v00 = r00 < nrows, v01 = r01 < nrows;
        bool v10 = r10 < nrows, v11 = r11 < nrows;

        float acc[2][8][4];
        #pragma unroll
        for (int s = 0; s < 2; s++)
            #pragma unroll
            for (int nt = 0; nt < 8; nt++)
                #pragma unroll
                for (int j = 0; j < 4; j++) acc[s][nt][j] = 0.0f;

        #pragma unroll
        for (int kt = 0; kt < 8; kt++) {
            int p0 = kt * 8 + qk;
            int p1 = p0 + 4;
            uint32_t ah0[4], al0[4], ah1[4], al1[4];
            ah0[0] = v00 ? Ahi[(long)r00 * NPAIRS + p0] : 0u;
            ah0[1] = v01 ? Ahi[(long)r01 * NPAIRS + p0] : 0u;
            ah0[2] = v00 ? Ahi[(long)r00 * NPAIRS + p1] : 0u;
            ah0[3] = v01 ? Ahi[(long)r01 * NPAIRS + p1] : 0u;
            al0[0] = v00 ? Alo[(long)r00 * NPAIRS + p0] : 0u;
            al0[1] = v01 ? Alo[(long)r01 * NPAIRS + p0] : 0u;
            al0[2] = v00 ? Alo[(long)r00 * NPAIRS + p1] : 0u;
            al0[3] = v01 ? Alo[(long)r01 * NPAIRS + p1] : 0u;
            ah1[0] = v10 ? Ahi[(long)r10 * NPAIRS + p0] : 0u;
            ah1[1] = v11 ? Ahi[(long)r11 * NPAIRS + p0] : 0u;
            ah1[2] = v10 ? Ahi[(long)r10 * NPAIRS + p1] : 0u;
            ah1[3] = v11 ? Ahi[(long)r11 * NPAIRS + p1] : 0u;
            al1[0] = v10 ? Alo[(long)r10 * NPAIRS + p0] : 0u;
            al1[1] = v11 ? Alo[(long)r11 * NPAIRS + p0] : 0u;
            al1[2] = v10 ? Alo[(long)r10 * NPAIRS + p1] : 0u;
            al1[3] = v11 ? Alo[(long)r11 * NPAIRS + p1] : 0u;

            #pragma unroll
            for (int nt = 0; nt < 8; nt++) {
                int n = cgrp * 64 + nt * 8 + qr;
                int o = n * SW_STR + kt * 8 + 2 * qk;
                uint2 BH = *reinterpret_cast<const uint2*>(&sWhi[o]);
                uint2 BL = *reinterpret_cast<const uint2*>(&sWlo[o]);
                uint32_t bh[2] = { BH.x, BH.y };
                uint32_t bl[2] = { BL.x, BL.y };
                mma_bf16(acc[0][nt], ah0, bh);
                mma_bf16(acc[0][nt], al0, bh);
                mma_bf16(acc[0][nt], ah0, bl);
                mma_bf16(acc[1][nt], ah1, bh);
                mma_bf16(acc[1][nt], al1, bh);
                mma_bf16(acc[1][nt], ah1, bl);
            }
        }

        #pragma unroll
        for (int nt = 0; nt < 8; nt++) {
            int col = cgrp * 64 + nt * 8 + 2 * qk;
            if (v00) *reinterpret_cast<float2*>(C + (long)r00 * D + col) =
                         make_float2(acc[0][nt][0], acc[0][nt][1]);
            if (v01) *reinterpret_cast<float2*>(C + (long)r01 * D + col) =
                         make_float2(acc[0][nt][2], acc[0][nt][3]);
            if (v10) *reinterpret_cast<float2*>(C + (long)r10 * D + col) =
                         make_float2(acc[1][nt][0], acc[1][nt][1]);
            if (v11) *reinterpret_cast<float2*>(C + (long)r11 * D + col) =
                         make_float2(acc[1][nt][2], acc[1][nt][3]);
        }
    }
}

// ---------------- persistent fused message-passing layer ----------------
// grid=148, 512 thr (16 warps). Slots OUTER, tiles INNER (block tile = 256 rows).
// Edge slots iterate SORTED per-type compacted row lists (deg>0, ascending src).
#define MPP_THREADS 512
#define MPP_GRID    148
#define WP_STR      72
#define W_TILE      (D * WP_STR)
#define STG_STR     72
#define MPP_SMEM    ((4 * W_TILE + 16 * 16 * STG_STR) * 4)

__global__ void __launch_bounds__(MPP_THREADS, 1)
mp_p_kernel(const uint32_t* __restrict__ Ahi, const uint32_t* __restrict__ Alo,
            const uint32_t* __restrict__ Whi, const uint32_t* __restrict__ Wlo,
            int layer,
            const int* __restrict__ off, const int* __restrict__ deg,
            const int* __restrict__ dstA,
            const int* __restrict__ rstart, const int* __restrict__ rlist,
            float* __restrict__ tmp, int nrows) {
    extern __shared__ uint32_t sm[];
    float* stage = reinterpret_cast<float*>(sm + 4 * W_TILE);
    uint32_t sbase = smem_u32(sm);

    int tid  = threadIdx.x;
    int wid  = tid >> 5;
    int lane = tid & 31;
    int rg = wid >> 1;
    int ch = wid & 1;
    int qr = lane >> 2;
    int qk = lane & 3;

    auto slot_of = [&](int s) {
        return (s == 0) ? (3 + layer) : (7 + layer * NTYPES + s - 1);
    };
    auto cp_w = [&](int s, int b) {
        const uint32_t* wh = Whi + (long)slot_of(s) * D * NPAIRS;
        const uint32_t* wl = Wlo + (long)slot_of(s) * D * NPAIRS;
        uint32_t bh = sbase + (uint32_t)(2 * b)     * W_TILE * 4u;
        uint32_t bl = sbase + (uint32_t)(2 * b + 1) * W_TILE * 4u;
        for (int i = tid * 4; i < D * NPAIRS; i += MPP_THREADS * 4) {
            int c = i >> 6, ip = i & 63;
            uint32_t o = (uint32_t)(c * WP_STR + ip) * 4u;
            cp16(bh + o, wh + i);
            cp16(bl + o, wl + i);
        }
        asm volatile("cp.async.commit_group;" ::: "memory");
    };

    cp_w(0, 0);

    for (int s = 0; s < 15; s++) {
        asm volatile("cp.async.wait_group 0;" ::: "memory");
        __syncthreads();
        if (s < 14) cp_w(s + 1, (s + 1) & 1);

        const uint32_t* sWhi = sm + (size_t)(2 * (s & 1))     * W_TILE;
        const uint32_t* sWlo = sm + (size_t)(2 * (s & 1) + 1) * W_TILE;
        int t = s - 1;
        int start = (s == 0) ? 0 : __ldg(rstart + t);
        int m     = (s == 0) ? nrows : (__ldg(rstart + t + 1) - start);
        const int* rl = rlist + start;
        int ntl = (m + 255) >> 8;

        for (int tile = blockIdx.x; tile < ntl; tile += MPP_GRID) {
            int rb = tile * 256 + rg * 32;
            int i00 = rb + qr;
            int i01 = rb + qr + 8;
            int i10 = rb + 16 + qr;
            int i11 = rb + 16 + qr + 8;
            bool v00 = i00 < m, v01 = i01 < m;
            bool v10 = i10 < m, v11 = i11 < m;
            int r00, r01, r10, r11;
            if (s == 0) {
                r00 = i00; r01 = i01; r10 = i10; r11 = i11;
            } else {
                r00 = v00 ? __ldg(rl + i00) : 0;
                r01 = v01 ? __ldg(rl + i01) : 0;
                r10 = v10 ? __ldg(rl + i10) : 0;
                r11 = v11 ? __ldg(rl + i11) : 0;
            }

            float acc[2][8][4];
            #pragma unroll
            for (int s2 = 0; s2 < 2; s2++)
                #pragma unroll
                for (int nt = 0; nt < 8; nt++)
                    #pragma unroll
                    for (int j = 0; j < 4; j++) acc[s2][nt][j] = 0.0f;

            #pragma unroll 2
            for (int kt = 0; kt < 8; kt++) {
                int p0 = kt * 8 + qk;
                int p1 = p0 + 4;
                uint32_t ah0[4], al0[4], ah1[4], al1[4];
                ah0[0] = v00 ? Ahi[(long)r00 * NPAIRS + p0] : 0u;
                ah0[1] = v01 ? Ahi[(long)r01 * NPAIRS + p0] : 0u;
                ah0[2] = v00 ? Ahi[(long)r00 * NPAIRS + p1] : 0u;
                ah0[3] = v01 ? Ahi[(long)r01 * NPAIRS + p1] : 0u;
                al0[0] = v00 ? Alo[(long)r00 * NPAIRS + p0] : 0u;
                al0[1] = v01 ? Alo[(long)r01 * NPAIRS + p0] : 0u;
                al0[2] = v00 ? Alo[(long)r00 * NPAIRS + p1] : 0u;
                al0[3] = v01 ? Alo[(long)r01 * NPAIRS + p1] : 0u;
                ah1[0] = v10 ? Ahi[(long)r10 * NPAIRS + p0] : 0u;
                ah1[1] = v11 ? Ahi[(long)r11 * NPAIRS + p0] : 0u;
                ah1[2] = v10 ? Ahi[(long)r10 * NPAIRS + p1] : 0u;
                ah1[3] = v11 ? Ahi[(long)r11 * NPAIRS + p1] : 0u;
                al1[0] = v10 ? Alo[(long)r10 * NPAIRS + p0] : 0u;
                al1[1] = v11 ? Alo[(long)r11 * NPAIRS + p0] : 0u;
                al1[2] = v10 ? Alo[(long)r10 * NPAIRS + p1] : 0u;
                al1[3] = v11 ? Alo[(long)r11 * NPAIRS + p1] : 0u;

                #pragma unroll
                for (int nt = 0; nt < 8; nt++) {
                    int n = ch * 64 + nt * 8 + qr;
                    int o = n * WP_STR + kt * 8 + 2 * qk;
                    uint2 BH = *reinterpret_cast<const uint2*>(&sWhi[o]);
                    uint2 BL = *reinterpret_cast<const uint2*>(&sWlo[o]);
                    uint32_t bh[2] = { BH.x, BH.y };
                    uint32_t bl[2] = { BL.x, BL.y };
                    mma_bf16(acc[0][nt], ah0, bh);
                    mma_bf16(acc[0][nt], al0, bh);
                    mma_bf16(acc[0][nt], ah0, bl);
                    mma_bf16(acc[1][nt], ah1, bh);
                    mma_bf16(acc[1][nt], al1, bh);
                    mma_bf16(acc[1][nt], ah1, bl);
                }
            }

            float* st = stage + wid * (16 * STG_STR);
            #pragma unroll
            for (int s2 = 0; s2 < 2; s2++) {
                #pragma unroll
                for (int nt = 0; nt < 8; nt++) {
                    int c2 = nt * 8 + 2 * qk;
                    *reinterpret_cast<float2*>(&st[qr * STG_STR + c2]) =
                        make_float2(acc[s2][nt][0], acc[s2][nt][1]);
                    *reinterpret_cast<float2*>(&st[(qr + 8) * STG_STR + c2]) =
                        make_float2(acc[s2][nt][2], acc[s2][nt][3]);
                }
                __syncwarp();

                int ibase = rb + s2 * 16;
                int colg = ch * 64 + (lane & 15) * 4;
                #pragma unroll
                for (int rr = 0; rr < 16; rr += 2) {
                    int lr  = rr + (lane >> 4);
                    int idx = ibase + lr;
                    float4 v = *reinterpret_cast<float4*>(
                        &st[lr * STG_STR + (lane & 15) * 4]);
                    if (idx < m) {
                        if (s == 0) {
                            red_v4(tmp + (long)idx * D + colg, v);
                        } else {
                            int row = __ldg(rl + idx);
                            long key = (long)t * NNODES + row;
                            int o0 = __ldg(off + key);
                            int dg = __ldg(deg + key);
                            for (int e = 0; e < dg; e++) {
                                int d = __ldg(dstA + o0 + e);
                                red_v4(tmp + (long)d * D + colg, v);
                            }
                        }
                    }
                }
                __syncwarp();
            }
        }
    }
}

// ---------------- GroupNorm helpers ----------------
__device__ __forceinline__ float warp_sum(float v) {
    #pragma unroll
    for (int o = 16; o > 0; o >>= 1) v += __shfl_xor_sync(0xffffffffu, v, o);
    return v;
}
__device__ __forceinline__ void store_split4(uint32_t* Ahi, uint32_t* Alo,
                                             int row, int lane, float4 y) {
    uint32_t h0, l0, h1, l1;
    split_pair(y.x, y.y, h0, l0);
    split_pair(y.z, y.w, h1, l1);
    *reinterpret_cast<uint2*>(Ahi + (long)row * NPAIRS + lane * 2) = make_uint2(h0, h1);
    *reinterpret_cast<uint2*>(Alo + (long)row * NPAIRS + lane * 2) = make_uint2(l0, l1);
}

__global__ void gn_kernel(const float* __restrict__ in,
                          const float* __restrict__ g, const float* __restrict__ b,
                          const float* __restrict__ resid,
                          float* __restrict__ out1, float* __restrict__ out2,
                          uint32_t* __restrict__ Ahi, uint32_t* __restrict__ Alo,
                          float* __restrict__ zbuf,
                          int do_relu) {
    int warp = (blockIdx.x * blockDim.x + threadIdx.x) >> 5;
    int lane = threadIdx.x & 31;
    if (warp >= NNODES) return;
    const float4 x = *reinterpret_cast<const float4*>(in + (long)warp * D + lane * 4);
    float s  = x.x + x.y + x.z + x.w;
    float ss = x.x * x.x + x.y * x.y + x.z * x.z + x.w * x.w;
    s  = warp_sum(s);
    ss = warp_sum(ss);
    float m   = s * (1.0f / 128.0f);
    float var = ss * (1.0f / 128.0f) - m * m;
    float inv = rsqrtf(var + 1e-5f);
    float4 gg = *reinterpret_cast<const float4*>(g + lane * 4);
    float4 bb = *reinterpret_cast<const float4*>(b + lane * 4);
    float4 y;
    y.x = fmaf((x.x - m) * inv, gg.x, bb.x);
    y.y = fmaf((x.y - m) * inv, gg.y, bb.y);
    y.z = fmaf((x.z - m) * inv, gg.z, bb.z);
    y.w = fmaf((x.w - m) * inv, gg.w, bb.w);
    if (resid) {
        float4 r = *reinterpret_cast<const float4*>(resid + (long)warp * D + lane * 4);
        y.x += r.x; y.y += r.y; y.z += r.z; y.w += r.w;
    }
    if (do_relu) {
        y.x = fmaxf(y.x, 0.0f); y.y = fmaxf(y.y, 0.0f);
        y.z = fmaxf(y.z, 0.0f); y.w = fmaxf(y.w, 0.0f);
    }
    if (out1)
        *reinterpret_cast<float4*>(out1 + (long)warp * D + lane * 4) = y;
    if (out2)
        *reinterpret_cast<float4*>(out2 + (long)warp * D + lane * 4) = y;
    if (Ahi) store_split4(Ahi, Alo, warp, lane, y);
    if (zbuf)
        *reinterpret_cast<float4*>(zbuf + (long)warp * D + lane * 4) =
            make_float4(0.f, 0.f, 0.f, 0.f);
}

__global__ void gn2_kernel(const float* __restrict__ inA,
                           const float* __restrict__ gA, const float* __restrict__ bA,
                           const float* __restrict__ inB,
                           const float* __restrict__ gB, const float* __restrict__ bB,
                           uint32_t* __restrict__ Ahi, uint32_t* __restrict__ Alo) {
    int warp = (blockIdx.x * blockDim.x + threadIdx.x) >> 5;
    int lane = threadIdx.x & 31;
    if (warp >= NNODES) return;
    const float4 xa = *reinterpret_cast<const float4*>(inA + (long)warp * D + lane * 4);
    const float4 xb = *reinterpret_cast<const float4*>(inB + (long)warp * D + lane * 4);
    float sa  = xa.x + xa.y + xa.z + xa.w;
    float ssa = xa.x * xa.x + xa.y * xa.y + xa.z * xa.z + xa.w * xa.w;
    float sb  = xb.x + xb.y + xb.z + xb.w;
    float ssb = xb.x * xb.x + xb.y * xb.y + xb.z * xb.z + xb.w * xb.w;
    sa = warp_sum(sa); ssa = warp_sum(ssa);
    sb = warp_sum(sb); ssb = warp_sum(ssb);
    float ma = sa * (1.0f / 128.0f);
    float mb = sb * (1.0f / 128.0f);
    float ia = rsqrtf(ssa * (1.0f / 128.0f) - ma * ma + 1e-5f);
    float ib = rsqrtf(ssb * (1.0f / 128.0f) - mb * mb + 1e-5f);
    float4 ga4 = *reinterpret_cast<const float4*>(gA + lane * 4);
    float4 ba4 = *reinterpret_cast<const float4*>(bA + lane * 4);
    float4 gb4 = *reinterpret_cast<const float4*>(gB + lane * 4);
    float4 bb4 = *reinterpret_cast<const float4*>(bB + lane * 4);
    float4 y;
    y.x = fmaf((xa.x - ma) * ia, ga4.x, ba4.x) + fmaf((xb.x - mb) * ib, gb4.x, bb4.x);
    y.y = fmaf((xa.y - ma) * ia, ga4.y, ba4.y) + fmaf((xb.y - mb) * ib, gb4.y, bb4.y);
    y.z = fmaf((xa.z - ma) * ia, ga4.z, ba4.z) + fmaf((xb.z - mb) * ib, gb4.z, bb4.z);
    y.w = fmaf((xa.w - ma) * ia, ga4.w, ba4.w) + fmaf((xb.w - mb) * ib, gb4.w, bb4.w);
    y.x = fmaxf(y.x, 0.0f); y.y = fmaxf(y.y, 0.0f);
    y.z = fmaxf(y.z, 0.0f); y.w = fmaxf(y.w, 0.0f);
    store_split4(Ahi, Alo, warp, lane, y);
}

// ---------------- rank-4 update ----------------
__global__ void rank4_kernel(const float* __restrict__ nodes,
                             const float* __restrict__ metaW,
                             float* __restrict__ out) {
    int idx = blockIdx.x * blockDim.x + threadIdx.x;
    if (idx >= NNODES * D) return;
    int n = idx >> 7;
    int c = idx & 127;
    const float* wr = metaW + c * 132 + 128;
    const float* nd = nodes + n * 8 + 4;
    float s = fmaf(nd[0], wr[0], fmaf(nd[1], wr[1], fmaf(nd[2], wr[2], nd[3] * wr[3])));
    out[idx] += s;
}

// ---------------- final output ----------------
__global__ void copy_out_kernel(const float* __restrict__ feat,
                                const float* __restrict__ nodes,
                                float* __restrict__ out) {
    int idx = blockIdx.x * blockDim.x + threadIdx.x;
    const int F = NNODES * D;
    if (idx < F) {
        out[idx] = feat[idx];
    } else if (idx < F + NNODES * 2) {
        int j = idx - F;
        int n = j >> 1;
        int c = j & 1;
        out[idx] = nodes[n * 8 + c];
    }
}

// ---------------- host launcher ----------------
extern "C" void kernel_launch(void* const* d_in, const int* in_sizes, int n_in,
                              void* d_out, int out_size) {
    const float* nodes   = (const float*)d_in[0];
    const int*   indexes = (const int*)  d_in[1];
    const int*   mask    = (const int*)  d_in[2];
    const float* in1_W   = (const float*)d_in[3];
    const float* in1_b   = (const float*)d_in[4];
    const float* in2_W   = (const float*)d_in[5];
    const float* in_g    = (const float*)d_in[6];
    const float* in_bg   = (const float*)d_in[7];
    const float* seg1_W  = (const float*)d_in[8];
    const float* seg1_b  = (const float*)d_in[9];
    const float* seg2_W  = (const float*)d_in[10];
    const float* seg_g   = (const float*)d_in[11];
    const float* seg_bg  = (const float*)d_in[12];
    const float* meta_W  = (const float*)d_in[13];
    const float* meta_g  = (const float*)d_in[14];
    const float* meta_bg = (const float*)d_in[15];
    const float* ctr_W   = (const float*)d_in[16];
    const float* edge_W  = (const float*)d_in[17];
    const float* norm_g  = (const float*)d_in[18];
    const float* norm_bg = (const float*)d_in[19];
    const float* ctr2_W  = (const float*)d_in[20];
    const float* ctr2_g  = (const float*)d_in[21];
    const float* ctr2_bg = (const float*)d_in[22];
    float* out = (float*)d_out;

    float *feat, *res, *tmp;
    uint32_t *Whi, *Wlo, *Ahi, *Alo;
    int *deg, *off, *cur, *dstA, *bsum, *foff, *fbsum, *rstart, *rlist;
    cudaGetSymbolAddress((void**)&feat, g_feat);
    cudaGetSymbolAddress((void**)&res,  g_res);
    cudaGetSymbolAddress((void**)&tmp,  g_tmp);
    cudaGetSymbolAddress((void**)&Whi,  g_Whi);
    cudaGetSymbolAddress((void**)&Wlo,  g_Wlo);
    cudaGetSymbolAddress((void**)&Ahi,  g_Ahi);
    cudaGetSymbolAddress((void**)&Alo,  g_Alo);
    cudaGetSymbolAddress((void**)&deg,  g_deg);
    cudaGetSymbolAddress((void**)&off,  g_off);
    cudaGetSymbolAddress((void**)&cur,  g_cur);
    cudaGetSymbolAddress((void**)&dstA, g_dst);
    cudaGetSymbolAddress((void**)&bsum, g_bsum);
    cudaGetSymbolAddress((void**)&foff, g_foff);
    cudaGetSymbolAddress((void**)&fbsum,g_fbsum);
    cudaGetSymbolAddress((void**)&rstart,g_rstart);
    cudaGetSymbolAddress((void**)&rlist, g_rlist);
    float* Hbuf;
    cudaGetSymbolAddress((void**)&Hbuf, g_H);

    cudaFuncSetAttribute(gemm_tc_kernel,
                         cudaFuncAttributeMaxDynamicSharedMemorySize, TC_SMEM);
    cudaFuncSetAttribute(mp_p_kernel,
                         cudaFuncAttributeMaxDynamicSharedMemorySize, MPP_SMEM);

    const int lin_grid = (NNODES * NPAIRS + 255) / 256;
    const int gn_grid  = (NNODES * 32 + 255) / 256;
    const int sw_grid  = (NSLOTS * D * NPAIRS + 255) / 256;
    const int r4_grid  = (NNODES * D + 255) / 256;
    const int e_grid   = (NEDGES + 255) / 256;
    const int zn_grid  = (SCAN_N + 255) / 256;

    auto sWp = [&](int s) { return Whi + (long)s * D * NPAIRS; };
    auto sLp = [&](int s) { return Wlo + (long)s * D * NPAIRS; };

    // ---- CSR build (edge-major) + SORTED per-type row lists ----
    zero_deg_kernel<<<zn_grid, 256>>>(deg);
    deg_kernel<<<e_grid, 256>>>(indexes, mask, deg);
    scan1_kernel<<<SCAN_NBLK, 256>>>(deg, off, bsum, 0);
    scan2_kernel<<<1, 512>>>(bsum, SCAN_NBLK);
    scan3_kernel<<<zn_grid, 256>>>(off, bsum, cur);
    fill_kernel<<<e_grid, 256>>>(indexes, mask, cur, dstA);
    scan1_kernel<<<SCAN_NBLK, 256>>>(deg, foff, fbsum, 1);
    scan2_kernel<<<1, 512>>>(fbsum, SCAN_NBLK);
    scan3f_kernel<<<zn_grid, 256>>>(deg, foff, fbsum, rlist, rstart);

    // ---- pre-split weights (interleaved) ----
    split_w_kernel<<<sw_grid, 256>>>(in2_W, seg2_W, meta_W, ctr_W, edge_W, ctr2_W,
                                     Whi, Wlo);

    // ---- init: input + seg branches ----
    lin1_kernel<<<lin_grid, 256>>>(nodes, 0, in1_W, in1_b, Ahi, Alo);
    gemm_tc_kernel<<<TC_GRID, TC_THREADS, TC_SMEM>>>(Ahi, Alo, sWp(0), sLp(0), Hbuf, NNODES);
    lin1_kernel<<<lin_grid, 256>>>(nodes, 2, seg1_W, seg1_b, Ahi, Alo);
    gemm_tc_kernel<<<TC_GRID, TC_THREADS, TC_SMEM>>>(Ahi, Alo, sWp(1), sLp(1), res, NNODES);
    gn2_kernel<<<gn_grid, 256>>>(Hbuf, in_g, in_bg, res, seg_g, seg_bg, Ahi, Alo);

    // ---- meta ----
    gemm_tc_kernel<<<TC_GRID, TC_THREADS, TC_SMEM>>>(Ahi, Alo, sWp(2), sLp(2), tmp, NNODES);
    rank4_kernel<<<r4_grid, 256>>>(nodes, meta_W, tmp);
    gn_kernel<<<gn_grid, 256>>>(tmp, meta_g, meta_bg, nullptr, nullptr, res,
                                Ahi, Alo, tmp, 1);

    // ---- 4 message-passing layers ----
    for (int i = 0; i < 4; i++) {
        mp_p_kernel<<<MPP_GRID, MPP_THREADS, MPP_SMEM>>>(Ahi, Alo, Whi, Wlo, i,
                                                         off, deg, dstA, rstart, rlist,
                                                         tmp, NNODES);
        gn_kernel<<<gn_grid, 256>>>(tmp, norm_g + i * D, norm_bg + i * D,
                                    nullptr, nullptr, nullptr, Ahi, Alo, nullptr, 1);
        gemm_tc_kernel<<<TC_GRID, TC_THREADS, TC_SMEM>>>(
            Ahi, Alo, sWp(63 + i), sLp(63 + i), tmp, NNODES);
        gn_kernel<<<gn_grid, 256>>>(tmp, ctr2_g + i * D, ctr2_bg + i * D,
                                    res, (i == 3) ? feat : nullptr,
                                    (i < 3) ? res : nullptr, Ahi, Alo,
                                    (i < 3) ? tmp : nullptr, 1);
    }

    // ---- outputs ----
    int total = NNODES * D + NNODES * 2;
    copy_out_kernel<<<(total + 255) / 256, 256>>>(feat, nodes, out);
}

// round 15
// speedup vs baseline: 1.3713x; 1.1163x over previous
#include <cuda_runtime.h>
#include <cuda_bf16.h>
#include <math.h>
#include <stdint.h>

#define NNODES 100000
#define NEDGES 100000
#define D      128
#define NPAIRS 64
#define NTYPES 14
#define NSLOTS 67   // 0:in2 1:seg2 2:meta 3..6:ctr 7..62:edge 63..66:ctr2

#define SCAN_N   (NTYPES * NNODES)
#define SCAN_BLK 4096
#define SCAN_NBLK ((SCAN_N + SCAN_BLK - 1) / SCAN_BLK)

// ---------------- static device scratch ----------------
__device__ float    g_feat[NNODES * D];
__device__ float    g_res [NNODES * D];
__device__ float    g_tmp [NNODES * D];
__device__ uint32_t g_Ahi [NNODES * NPAIRS];
__device__ uint32_t g_Alo [NNODES * NPAIRS];
__device__ uint32_t g_Whi [NSLOTS * D * NPAIRS];   // pair-interleaved layout
__device__ uint32_t g_Wlo [NSLOTS * D * NPAIRS];
__device__ float    g_H  [NNODES * D];
__device__ int g_deg [SCAN_N];
__device__ int g_off [SCAN_N];
__device__ int g_cur [SCAN_N];
__device__ int g_dst [NTYPES * NEDGES];
__device__ int g_bsum [512];
__device__ int g_foff [SCAN_N];              // scan of (deg>0) flags
__device__ int g_fbsum[512];
__device__ int g_rstart[NTYPES + 1];         // per-type start into rlist
__device__ int g_rlist[SCAN_N];              // SORTED compacted src lists

// ---------------- generic helpers ----------------
__device__ __forceinline__ uint32_t pack_bf16x2(float e0, float e1) {
    uint32_t r;
    asm("cvt.rn.bf16x2.f32 %0, %1, %2;" : "=r"(r) : "f"(e1), "f"(e0));
    return r;
}
__device__ __forceinline__ void split_pair(float x0, float x1,
                                           uint32_t& hi, uint32_t& lo) {
    hi = pack_bf16x2(x0, x1);
    float h0 = __uint_as_float(hi << 16);
    float h1 = __uint_as_float(hi & 0xFFFF0000u);
    lo = pack_bf16x2(x0 - h0, x1 - h1);
}
__device__ __forceinline__ void mma_bf16(float* d, const uint32_t* a, const uint32_t* b) {
    asm volatile(
        "mma.sync.aligned.m16n8k16.row.col.f32.bf16.bf16.f32 "
        "{%0,%1,%2,%3}, {%4,%5,%6,%7}, {%8,%9}, {%0,%1,%2,%3};"
        : "+f"(d[0]), "+f"(d[1]), "+f"(d[2]), "+f"(d[3])
        : "r"(a[0]), "r"(a[1]), "r"(a[2]), "r"(a[3]), "r"(b[0]), "r"(b[1]));
}
__device__ __forceinline__ void red_v4(float* p, float4 v) {
    asm volatile("red.global.add.v4.f32 [%0], {%1, %2, %3, %4};"
                 :: "l"(p), "f"(v.x), "f"(v.y), "f"(v.z), "f"(v.w) : "memory");
}
__device__ __forceinline__ void cp16(uint32_t dst_smem, const void* src) {
    asm volatile("cp.async.ca.shared.global [%0], [%1], 16;" :: "r"(dst_smem), "l"(src));
}
__device__ __forceinline__ uint32_t smem_u32(const void* p) {
    uint32_t a;
    asm("{ .reg .u64 t; cvta.to.shared.u64 t, %1; cvt.u32.u64 %0, t; }" : "=r"(a) : "l"(p));
    return a;
}

// ---------------- CSR build (edge-major, coalesced) ----------------
__global__ void zero_deg_kernel(int* deg) {
    int i = blockIdx.x * blockDim.x + threadIdx.x;
    if (i < SCAN_N) deg[i] = 0;
}
__global__ void deg_kernel(const int* __restrict__ indexes,
                           const int* __restrict__ mask, int* __restrict__ deg) {
    int e = blockIdx.x * blockDim.x + threadIdx.x;
    if (e >= NEDGES) return;
    int4 v[7];
    const int4* row = reinterpret_cast<const int4*>(indexes + e * 28);
    #pragma unroll
    for (int i = 0; i < 7; i++) v[i] = __ldg(row + i);
    const int* vi = reinterpret_cast<const int*>(v);
    #pragma unroll
    for (int t = 0; t < NTYPES; t++) {
        if (e < __ldg(mask + t)) {
            int src = vi[2 * t + 1];
            atomicAdd(&deg[t * NNODES + src], 1);
        }
    }
}
// generic block scan: mode 0 -> scan deg values; mode 1 -> scan (deg>0) flags
__global__ void scan1_kernel(const int* __restrict__ deg, int* __restrict__ off,
                             int* __restrict__ bsum, int mode) {
    __shared__ int warp_tot[8];
    int b = blockIdx.x, tid = threadIdx.x;
    int base = b * SCAN_BLK + tid * 16;
    int v[16];
    int run = 0;
    #pragma unroll
    for (int i = 0; i < 16; i++) {
        int idx = base + i;
        int t = (idx < SCAN_N) ? deg[idx] : 0;
        if (mode) t = (t > 0) ? 1 : 0;
        v[i] = run;
        run += t;
    }
    int lane = tid & 31, w = tid >> 5;
    int x = run;
    #pragma unroll
    for (int o = 1; o < 32; o <<= 1) {
        int y = __shfl_up_sync(0xffffffffu, x, o);
        if (lane >= o) x += y;
    }
    if (lane == 31) warp_tot[w] = x;
    __syncthreads();
    int woff = 0;
    for (int i = 0; i < w; i++) woff += warp_tot[i];
    int excl = x - run + woff;
    #pragma unroll
    for (int i = 0; i < 16; i++)
        if (base + i < SCAN_N) off[base + i] = v[i] + excl;
    if (tid == 255) bsum[b] = excl + run;
}
__global__ void scan2_kernel(int* bsum, int n) {
    __shared__ int sm[512];
    int tid = threadIdx.x;
    int v = (tid < n) ? bsum[tid] : 0;
    sm[tid] = v;
    __syncthreads();
    for (int o = 1; o < 512; o <<= 1) {
        int t = (tid >= o) ? sm[tid - o] : 0;
        __syncthreads();
        sm[tid] += t;
        __syncthreads();
    }
    if (tid < n) bsum[tid] = sm[tid] - v;
}
__global__ void scan3_kernel(int* __restrict__ off, const int* __restrict__ bsum,
                             int* __restrict__ cur) {
    int i = blockIdx.x * blockDim.x + threadIdx.x;
    if (i >= SCAN_N) return;
    int o = off[i] + bsum[i / SCAN_BLK];
    off[i] = o;
    cur[i] = o;
}
// finalize flag scan: emit SORTED rlist + per-type starts
__global__ void scan3f_kernel(const int* __restrict__ deg,
                              const int* __restrict__ foff,
                              const int* __restrict__ fbsum,
                              int* __restrict__ rlist, int* __restrict__ rstart) {
    int i = blockIdx.x * blockDim.x + threadIdx.x;
    if (i >= SCAN_N) return;
    int fo = foff[i] + fbsum[i / SCAN_BLK];
    int t   = i / NNODES;
    int src = i - t * NNODES;
    int live = (deg[i] > 0) ? 1 : 0;
    if (live) rlist[fo] = src;
    if (src == 0) rstart[t] = fo;
    if (i == SCAN_N - 1) rstart[NTYPES] = fo + live;
}
__global__ void fill_kernel(const int* __restrict__ indexes,
                            const int* __restrict__ mask,
                            int* __restrict__ cur, int* __restrict__ dstA) {
    int e = blockIdx.x * blockDim.x + threadIdx.x;
    if (e >= NEDGES) return;
    int4 v[7];
    const int4* row = reinterpret_cast<const int4*>(indexes + e * 28);
    #pragma unroll
    for (int i = 0; i < 7; i++) v[i] = __ldg(row + i);
    const int* vi = reinterpret_cast<const int*>(v);
    #pragma unroll
    for (int t = 0; t < NTYPES; t++) {
        if (e < __ldg(mask + t)) {
            int src = vi[2 * t + 1];
            int dst = vi[2 * t];
            int pos = atomicAdd(&cur[t * NNODES + src], 1);
            dstA[pos] = dst;
        }
    }
}

// ---------------- pre-split weights (PAIR-INTERLEAVED gmem layout) -------------
__global__ void split_w_kernel(const float* __restrict__ in2,
                               const float* __restrict__ seg2,
                               const float* __restrict__ meta,
                               const float* __restrict__ ctr,
                               const float* __restrict__ edge,
                               const float* __restrict__ ctr2,
                               uint32_t* __restrict__ Whi,
                               uint32_t* __restrict__ Wlo) {
    int idx = blockIdx.x * blockDim.x + threadIdx.x;
    if (idx >= NSLOTS * D * NPAIRS) return;
    int slot = idx / (D * NPAIRS);
    int r    = idx - slot * (D * NPAIRS);
    int c    = r >> 6;
    int ip   = r & 63;
    int g  = ip >> 3;
    int w  = ip & 7;
    int qk = w >> 1;
    int j  = w & 1;
    int p  = 8 * g + qk + 4 * j;
    int k0 = 2 * p;
    float x0, x1;
    if      (slot == 0) { x0 = in2 [c * D + k0]; x1 = in2 [c * D + k0 + 1]; }
    else if (slot == 1) { x0 = seg2[c * D + k0]; x1 = seg2[c * D + k0 + 1]; }
    else if (slot == 2) { x0 = meta[c * 132 + k0]; x1 = meta[c * 132 + k0 + 1]; }
    else if (slot < 7)  { const float* wm = ctr  + (long)(slot - 3)  * D * D;
                          x0 = wm[c * D + k0]; x1 = wm[c * D + k0 + 1]; }
    else if (slot < 63) { const float* wm = edge + (long)(slot - 7)  * D * D;
                          x0 = wm[c * D + k0]; x1 = wm[c * D + k0 + 1]; }
    else                { const float* wm = ctr2 + (long)(slot - 63) * D * D;
                          x0 = wm[c * D + k0]; x1 = wm[c * D + k0 + 1]; }
    uint32_t hi, lo;
    split_pair(x0, x1, hi, lo);
    Whi[idx] = hi;
    Wlo[idx] = lo;
}

// ---------------- lin1 ----------------
__global__ void lin1_kernel(const float* __restrict__ nodes, int off,
                            const float* __restrict__ W1, const float* __restrict__ b1,
                            uint32_t* __restrict__ Ahi, uint32_t* __restrict__ Alo) {
    int idx = blockIdx.x * blockDim.x + threadIdx.x;
    if (idx >= NNODES * NPAIRS) return;
    int n = idx >> 6;
    int p = idx & 63;
    int j0 = 2 * p;
    float x0 = nodes[n * 8 + off];
    float x1 = nodes[n * 8 + off + 1];
    float v0 = fmaxf(fmaf(x0, W1[j0 * 2],     fmaf(x1, W1[j0 * 2 + 1], b1[j0])),     0.0f);
    float v1 = fmaxf(fmaf(x0, W1[j0 * 2 + 2], fmaf(x1, W1[j0 * 2 + 3], b1[j0 + 1])), 0.0f);
    uint32_t hi, lo;
    split_pair(v0, v1, hi, lo);
    Ahi[idx] = hi;
    Alo[idx] = lo;
}

// ---------------- GEMM (init/meta/ctr2): interleaved W, LDS.64 B-frags --------
#define TC_THREADS 256
#define SW_STR     72
#define TC_SMEM    (2 * D * SW_STR * 4)
#define TC_GRID    296

__global__ void __launch_bounds__(TC_THREADS, 2)
gemm_tc_kernel(const uint32_t* __restrict__ Ahi, const uint32_t* __restrict__ Alo,
               const uint32_t* __restrict__ Whi, const uint32_t* __restrict__ Wlo,
               float* __restrict__ C, int nrows) {
    extern __shared__ uint32_t sm[];
    uint32_t* sWhi = sm;
    uint32_t* sWlo = sm + D * SW_STR;
    int tid = threadIdx.x;

    for (int idx = tid; idx < D * NPAIRS; idx += TC_THREADS) {
        int c = idx >> 6;
        int ip = idx & 63;
        sWhi[c * SW_STR + ip] = Whi[idx];
        sWlo[c * SW_STR + ip] = Wlo[idx];
    }
    __syncthreads();

    int wid  = tid >> 5;
    int lane = tid & 31;
    int rgrp = wid >> 1;
    int cgrp = wid & 1;
    int qr = lane >> 2;
    int qk = lane & 3;

    int ntiles = (nrows + 127) / 128;
    for (int tile = blockIdx.x; tile < ntiles; tile += gridDim.x) {
        int rbase = tile * 128 + rgrp * 32;
        int r00 = rbase + qr;
        int r01 = rbase + qr + 8;
        int r10 = rbase + 16 + qr;
        int r11 = rbase + 16 + qr + 8;
        bool v00 = r00 < nrows, v01 = r01 < nrows;
        bool v10 = r10 < nrows, v11 = r11 < nrows;

        float acc[2][8][4];
        #pragma unroll
        for (int s = 0; s < 2; s++)
            #pragma unroll
            for (int nt = 0; nt < 8; nt++)
                #pragma unroll
                for (int j = 0; j < 4; j++) acc[s][nt][j] = 0.0f;

        #pragma unroll
        for (int kt = 0; kt < 8; kt++) {
            int p0 = kt * 8 + qk;
            int p1 = p0 + 4;
            uint32_t ah0[4], al0[4], ah1[4], al1[4];
            ah0[0] = v00 ? Ahi[(long)r00 * NPAIRS + p0] : 0u;
            ah0[1] = v01 ? Ahi[(long)r01 * NPAIRS + p0] : 0u;
            ah0[2] = v00 ? Ahi[(long)r00 * NPAIRS + p1] : 0u;
            ah0[3] = v01 ? Ahi[(long)r01 * NPAIRS + p1] : 0u;
            al0[0] = v00 ? Alo[(long)r00 * NPAIRS + p0] : 0u;
            al0[1] = v01 ? Alo[(long)r01 * NPAIRS + p0] : 0u;
            al0[2] = v00 ? Alo[(long)r00 * NPAIRS + p1] : 0u;
            al0[3] = v01 ? Alo[(long)r01 * NPAIRS + p1] : 0u;
            ah1[0] = v10 ? Ahi[(long)r10 * NPAIRS + p0] : 0u;
            ah1[1] = v11 ? Ahi[(long)r11 * NPAIRS + p0] : 0u;
            ah1[2] = v10 ? Ahi[(long)r10 * NPAIRS + p1] : 0u;
            ah1[3] = v11 ? Ahi[(long)r11 * NPAIRS + p1] : 0u;
            al1[0] = v10 ? Alo[(long)r10 * NPAIRS + p0] : 0u;
            al1[1] = v11 ? Alo[(long)r11 * NPAIRS + p0] : 0u;
            al1[2] = v10 ? Alo[(long)r10 * NPAIRS + p1] : 0u;
            al1[3] = v11 ? Alo[(long)r11 * NPAIRS + p1] : 0u;

            #pragma unroll
            for (int nt = 0; nt < 8; nt++) {
                int n = cgrp * 64 + nt * 8 + qr;
                int o = n * SW_STR + kt * 8 + 2 * qk;
                uint2 BH = *reinterpret_cast<const uint2*>(&sWhi[o]);
                uint2 BL = *reinterpret_cast<const uint2*>(&sWlo[o]);
                uint32_t bh[2] = { BH.x, BH.y };
                uint32_t bl[2] = { BL.x, BL.y };
                mma_bf16(acc[0][nt], ah0, bh);
                mma_bf16(acc[0][nt], al0, bh);
                mma_bf16(acc[0][nt], ah0, bl);
                mma_bf16(acc[1][nt], ah1, bh);
                mma_bf16(acc[1][nt], al1, bh);
                mma_bf16(acc[1][nt], ah1, bl);
            }
        }

        #pragma unroll
        for (int nt = 0; nt < 8; nt++) {
            int col = cgrp * 64 + nt * 8 + 2 * qk;
            if (v00) *reinterpret_cast<float2*>(C + (long)r00 * D + col) =
                         make_float2(acc[0][nt][0], acc[0][nt][1]);
            if (v01) *reinterpret_cast<float2*>(C + (long)r01 * D + col) =
                         make_float2(acc[0][nt][2], acc[0][nt][3]);
            if (v10) *reinterpret_cast<float2*>(C + (long)r10 * D + col) =
                         make_float2(acc[1][nt][0], acc[1][nt][1]);
            if (v11) *reinterpret_cast<float2*>(C + (long)r11 * D + col) =
                         make_float2(acc[1][nt][2], acc[1][nt][3]);
        }
    }
}

// ---------------- persistent fused message-passing layer ----------------
// grid=148, 512 thr (16 warps). Slots OUTER, tiles INNER (block tile = 256 rows).
// Edge slots iterate SORTED per-type compacted row lists (deg>0, ascending src).
// Tile origin ROTATED per slot to balance remainder tiles across blocks.
#define MPP_THREADS 512
#define MPP_GRID    148
#define WP_STR      72
#define W_TILE      (D * WP_STR)
#define STG_STR     72
#define MPP_SMEM    ((4 * W_TILE + 16 * 16 * STG_STR) * 4)

__global__ void __launch_bounds__(MPP_THREADS, 1)
mp_p_kernel(const uint32_t* __restrict__ Ahi, const uint32_t* __restrict__ Alo,
            const uint32_t* __restrict__ Whi, const uint32_t* __restrict__ Wlo,
            int layer,
            const int* __restrict__ off, const int* __restrict__ deg,
            const int* __restrict__ dstA,
            const int* __restrict__ rstart, const int* __restrict__ rlist,
            float* __restrict__ tmp, int nrows) {
    extern __shared__ uint32_t sm[];
    float* stage = reinterpret_cast<float*>(sm + 4 * W_TILE);
    uint32_t sbase = smem_u32(sm);

    int tid  = threadIdx.x;
    int wid  = tid >> 5;
    int lane = tid & 31;
    int rg = wid >> 1;
    int ch = wid & 1;
    int qr = lane >> 2;
    int qk = lane & 3;

    auto slot_of = [&](int s) {
        return (s == 0) ? (3 + layer) : (7 + layer * NTYPES + s - 1);
    };
    auto cp_w = [&](int s, int b) {
        const uint32_t* wh = Whi + (long)slot_of(s) * D * NPAIRS;
        const uint32_t* wl = Wlo + (long)slot_of(s) * D * NPAIRS;
        uint32_t bh = sbase + (uint32_t)(2 * b)     * W_TILE * 4u;
        uint32_t bl = sbase + (uint32_t)(2 * b + 1) * W_TILE * 4u;
        for (int i = tid * 4; i < D * NPAIRS; i += MPP_THREADS * 4) {
            int c = i >> 6, ip = i & 63;
            uint32_t o = (uint32_t)(c * WP_STR + ip) * 4u;
            cp16(bh + o, wh + i);
            cp16(bl + o, wl + i);
        }
        asm volatile("cp.async.commit_group;" ::: "memory");
    };

    cp_w(0, 0);

    for (int s = 0; s < 15; s++) {
        asm volatile("cp.async.wait_group 0;" ::: "memory");
        __syncthreads();
        if (s < 14) cp_w(s + 1, (s + 1) & 1);

        const uint32_t* sWhi = sm + (size_t)(2 * (s & 1))     * W_TILE;
        const uint32_t* sWlo = sm + (size_t)(2 * (s & 1) + 1) * W_TILE;
        int t = s - 1;
        int start = (s == 0) ? 0 : __ldg(rstart + t);
        int m     = (s == 0) ? nrows : (__ldg(rstart + t + 1) - start);
        const int* rl = rlist + start;
        int ntl = (m + 255) >> 8;

        // rotated tile origin: balances per-slot remainder tiles across blocks
        int rot = (blockIdx.x + s * 53) % MPP_GRID;

        for (int tile = rot; tile < ntl; tile += MPP_GRID) {
            int rb = tile * 256 + rg * 32;
            int i00 = rb + qr;
            int i01 = rb + qr + 8;
            int i10 = rb + 16 + qr;
            int i11 = rb + 16 + qr + 8;
            bool v00 = i00 < m, v01 = i01 < m;
            bool v10 = i10 < m, v11 = i11 < m;
            int r00, r01, r10, r11;
            if (s == 0) {
                r00 = i00; r01 = i01; r10 = i10; r11 = i11;
            } else {
                r00 = v00 ? __ldg(rl + i00) : 0;
                r01 = v01 ? __ldg(rl + i01) : 0;
                r10 = v10 ? __ldg(rl + i10) : 0;
                r11 = v11 ? __ldg(rl + i11) : 0;
            }

            float acc[2][8][4];
            #pragma unroll
            for (int s2 = 0; s2 < 2; s2++)
                #pragma unroll
                for (int nt = 0; nt < 8; nt++)
                    #pragma unroll
                    for (int j = 0; j < 4; j++) acc[s2][nt][j] = 0.0f;

            #pragma unroll 2
            for (int kt = 0; kt < 8; kt++) {
                int p0 = kt * 8 + qk;
                int p1 = p0 + 4;
                uint32_t ah0[4], al0[4], ah1[4], al1[4];
                ah0[0] = v00 ? Ahi[(long)r00 * NPAIRS + p0] : 0u;
                ah0[1] = v01 ? Ahi[(long)r01 * NPAIRS + p0] : 0u;
                ah0[2] = v00 ? Ahi[(long)r00 * NPAIRS + p1] : 0u;
                ah0[3] = v01 ? Ahi[(long)r01 * NPAIRS + p1] : 0u;
                al0[0] = v00 ? Alo[(long)r00 * NPAIRS + p0] : 0u;
                al0[1] = v01 ? Alo[(long)r01 * NPAIRS + p0] : 0u;
                al0[2] = v00 ? Alo[(long)r00 * NPAIRS + p1] : 0u;
                al0[3] = v01 ? Alo[(long)r01 * NPAIRS + p1] : 0u;
                ah1[0] = v10 ? Ahi[(long)r10 * NPAIRS + p0] : 0u;
                ah1[1] = v11 ? Ahi[(long)r11 * NPAIRS + p0] : 0u;
                ah1[2] = v10 ? Ahi[(long)r10 * NPAIRS + p1] : 0u;
                ah1[3] = v11 ? Ahi[(long)r11 * NPAIRS + p1] : 0u;
                al1[0] = v10 ? Alo[(long)r10 * NPAIRS + p0] : 0u;
                al1[1] = v11 ? Alo[(long)r11 * NPAIRS + p0] : 0u;
                al1[2] = v10 ? Alo[(long)r10 * NPAIRS + p1] : 0u;
                al1[3] = v11 ? Alo[(long)r11 * NPAIRS + p1] : 0u;

                #pragma unroll
                for (int nt = 0; nt < 8; nt++) {
                    int n = ch * 64 + nt * 8 + qr;
                    int o = n * WP_STR + kt * 8 + 2 * qk;
                    uint2 BH = *reinterpret_cast<const uint2*>(&sWhi[o]);
                    uint2 BL = *reinterpret_cast<const uint2*>(&sWlo[o]);
                    uint32_t bh[2] = { BH.x, BH.y };
                    uint32_t bl[2] = { BL.x, BL.y };
                    mma_bf16(acc[0][nt], ah0, bh);
                    mma_bf16(acc[0][nt], al0, bh);
                    mma_bf16(acc[0][nt], ah0, bl);
                    mma_bf16(acc[1][nt], ah1, bh);
                    mma_bf16(acc[1][nt], al1, bh);
                    mma_bf16(acc[1][nt], ah1, bl);
                }
            }

            float* st = stage + wid * (16 * STG_STR);
            #pragma unroll
            for (int s2 = 0; s2 < 2; s2++) {
                #pragma unroll
                for (int nt = 0; nt < 8; nt++) {
                    int c2 = nt * 8 + 2 * qk;
                    *reinterpret_cast<float2*>(&st[qr * STG_STR + c2]) =
                        make_float2(acc[s2][nt][0], acc[s2][nt][1]);
                    *reinterpret_cast<float2*>(&st[(qr + 8) * STG_STR + c2]) =
                        make_float2(acc[s2][nt][2], acc[s2][nt][3]);
                }
                __syncwarp();

                int ibase = rb + s2 * 16;
                int colg = ch * 64 + (lane & 15) * 4;
                #pragma unroll
                for (int rr = 0; rr < 16; rr += 2) {
                    int lr  = rr + (lane >> 4);
                    int idx = ibase + lr;
                    float4 v = *reinterpret_cast<float4*>(
                        &st[lr * STG_STR + (lane & 15) * 4]);
                    if (idx < m) {
                        if (s == 0) {
                            red_v4(tmp + (long)idx * D + colg, v);
                        } else {
                            int row = __ldg(rl + idx);
                            long key = (long)t * NNODES + row;
                            int o0 = __ldg(off + key);
                            int dg = __ldg(deg + key);
                            for (int e = 0; e < dg; e++) {
                                int d = __ldg(dstA + o0 + e);
                                red_v4(tmp + (long)d * D + colg, v);
                            }
                        }
                    }
                }
                __syncwarp();
            }
        }
    }
}

// ---------------- GroupNorm helpers ----------------
__device__ __forceinline__ float warp_sum(float v) {
    #pragma unroll
    for (int o = 16; o > 0; o >>= 1) v += __shfl_xor_sync(0xffffffffu, v, o);
    return v;
}
__device__ __forceinline__ void store_split4(uint32_t* Ahi, uint32_t* Alo,
                                             int row, int lane, float4 y) {
    uint32_t h0, l0, h1, l1;
    split_pair(y.x, y.y, h0, l0);
    split_pair(y.z, y.w, h1, l1);
    *reinterpret_cast<uint2*>(Ahi + (long)row * NPAIRS + lane * 2) = make_uint2(h0, h1);
    *reinterpret_cast<uint2*>(Alo + (long)row * NPAIRS + lane * 2) = make_uint2(l0, l1);
}

__global__ void gn_kernel(const float* __restrict__ in,
                          const float* __restrict__ g, const float* __restrict__ b,
                          const float* __restrict__ resid,
                          float* __restrict__ out1, float* __restrict__ out2,
                          uint32_t* __restrict__ Ahi, uint32_t* __restrict__ Alo,
                          float* __restrict__ zbuf,
                          int do_relu) {
    int warp = (blockIdx.x * blockDim.x + threadIdx.x) >> 5;
    int lane = threadIdx.x & 31;
    if (warp >= NNODES) return;
    const float4 x = *reinterpret_cast<const float4*>(in + (long)warp * D + lane * 4);
    float s  = x.x + x.y + x.z + x.w;
    float ss = x.x * x.x + x.y * x.y + x.z * x.z + x.w * x.w;
    s  = warp_sum(s);
    ss = warp_sum(ss);
    float m   = s * (1.0f / 128.0f);
    float var = ss * (1.0f / 128.0f) - m * m;
    float inv = rsqrtf(var + 1e-5f);
    float4 gg = *reinterpret_cast<const float4*>(g + lane * 4);
    float4 bb = *reinterpret_cast<const float4*>(b + lane * 4);
    float4 y;
    y.x = fmaf((x.x - m) * inv, gg.x, bb.x);
    y.y = fmaf((x.y - m) * inv, gg.y, bb.y);
    y.z = fmaf((x.z - m) * inv, gg.z, bb.z);
    y.w = fmaf((x.w - m) * inv, gg.w, bb.w);
    if (resid) {
        float4 r = *reinterpret_cast<const float4*>(resid + (long)warp * D + lane * 4);
        y.x += r.x; y.y += r.y; y.z += r.z; y.w += r.w;
    }
    if (do_relu) {
        y.x = fmaxf(y.x, 0.0f); y.y = fmaxf(y.y, 0.0f);
        y.z = fmaxf(y.z, 0.0f); y.w = fmaxf(y.w, 0.0f);
    }
    if (out1)
        *reinterpret_cast<float4*>(out1 + (long)warp * D + lane * 4) = y;
    if (out2)
        *reinterpret_cast<float4*>(out2 + (long)warp * D + lane * 4) = y;
    if (Ahi) store_split4(Ahi, Alo, warp, lane, y);
    if (zbuf)
        *reinterpret_cast<float4*>(zbuf + (long)warp * D + lane * 4) =
            make_float4(0.f, 0.f, 0.f, 0.f);
}

__global__ void gn2_kernel(const float* __restrict__ inA,
                           const float* __restrict__ gA, const float* __restrict__ bA,
                           const float* __restrict__ inB,
                           const float* __restrict__ gB, const float* __restrict__ bB,
                           uint32_t* __restrict__ Ahi, uint32_t* __restrict__ Alo) {
    int warp = (blockIdx.x * blockDim.x + threadIdx.x) >> 5;
    int lane = threadIdx.x & 31;
    if (warp >= NNODES) return;
    const float4 xa = *reinterpret_cast<const float4*>(inA + (long)warp * D + lane * 4);
    const float4 xb = *reinterpret_cast<const float4*>(inB + (long)warp * D + lane * 4);
    float sa  = xa.x + xa.y + xa.z + xa.w;
    float ssa = xa.x * xa.x + xa.y * xa.y + xa.z * xa.z + xa.w * xa.w;
    float sb  = xb.x + xb.y + xb.z + xb.w;
    float ssb = xb.x * xb.x + xb.y * xb.y + xb.z * xb.z + xb.w * xb.w;
    sa = warp_sum(sa); ssa = warp_sum(ssa);
    sb = warp_sum(sb); ssb = warp_sum(ssb);
    float ma = sa * (1.0f / 128.0f);
    float mb = sb * (1.0f / 128.0f);
    float ia = rsqrtf(ssa * (1.0f / 128.0f) - ma * ma + 1e-5f);
    float ib = rsqrtf(ssb * (1.0f / 128.0f) - mb * mb + 1e-5f);
    float4 ga4 = *reinterpret_cast<const float4*>(gA + lane * 4);
    float4 ba4 = *reinterpret_cast<const float4*>(bA + lane * 4);
    float4 gb4 = *reinterpret_cast<const float4*>(gB + lane * 4);
    float4 bb4 = *reinterpret_cast<const float4*>(bB + lane * 4);
    float4 y;
    y.x = fmaf((xa.x - ma) * ia, ga4.x, ba4.x) + fmaf((xb.x - mb) * ib, gb4.x, bb4.x);
    y.y = fmaf((xa.y - ma) * ia, ga4.y, ba4.y) + fmaf((xb.y - mb) * ib, gb4.y, bb4.y);
    y.z = fmaf((xa.z - ma) * ia, ga4.z, ba4.z) + fmaf((xb.z - mb) * ib, gb4.z, bb4.z);
    y.w = fmaf((xa.w - ma) * ia, ga4.w, ba4.w) + fmaf((xb.w - mb) * ib, gb4.w, bb4.w);
    y.x = fmaxf(y.x, 0.0f); y.y = fmaxf(y.y, 0.0f);
    y.z = fmaxf(y.z, 0.0f); y.w = fmaxf(y.w, 0.0f);
    store_split4(Ahi, Alo, warp, lane, y);
}

// ---------------- rank-4 update ----------------
__global__ void rank4_kernel(const float* __restrict__ nodes,
                             const float* __restrict__ metaW,
                             float* __restrict__ out) {
    int idx = blockIdx.x * blockDim.x + threadIdx.x;
    if (idx >= NNODES * D) return;
    int n = idx >> 7;
    int c = idx & 127;
    const float* wr = metaW + c * 132 + 128;
    const float* nd = nodes + n * 8 + 4;
    float s = fmaf(nd[0], wr[0], fmaf(nd[1], wr[1], fmaf(nd[2], wr[2], nd[3] * wr[3])));
    out[idx] += s;
}

// ---------------- final output ----------------
__global__ void copy_out_kernel(const float* __restrict__ feat,
                                const float* __restrict__ nodes,
                                float* __restrict__ out) {
    int idx = blockIdx.x * blockDim.x + threadIdx.x;
    const int F = NNODES * D;
    if (idx < F) {
        out[idx] = feat[idx];
    } else if (idx < F + NNODES * 2) {
        int j = idx - F;
        int n = j >> 1;
        int c = j & 1;
        out[idx] = nodes[n * 8 + c];
    }
}

// ---------------- host launcher ----------------
extern "C" void kernel_launch(void* const* d_in, const int* in_sizes, int n_in,
                              void* d_out, int out_size) {
    const float* nodes   = (const float*)d_in[0];
    const int*   indexes = (const int*)  d_in[1];
    const int*   mask    = (const int*)  d_in[2];
    const float* in1_W   = (const float*)d_in[3];
    const float* in1_b   = (const float*)d_in[4];
    const float* in2_W   = (const float*)d_in[5];
    const float* in_g    = (const float*)d_in[6];
    const float* in_bg   = (const float*)d_in[7];
    const float* seg1_W  = (const float*)d_in[8];
    const float* seg1_b  = (const float*)d_in[9];
    const float* seg2_W  = (const float*)d_in[10];
    const float* seg_g   = (const float*)d_in[11];
    const float* seg_bg  = (const float*)d_in[12];
    const float* meta_W  = (const float*)d_in[13];
    const float* meta_g  = (const float*)d_in[14];
    const float* meta_bg = (const float*)d_in[15];
    const float* ctr_W   = (const float*)d_in[16];
    const float* edge_W  = (const float*)d_in[17];
    const float* norm_g  = (const float*)d_in[18];
    const float* norm_bg = (const float*)d_in[19];
    const float* ctr2_W  = (const float*)d_in[20];
    const float* ctr2_g  = (const float*)d_in[21];
    const float* ctr2_bg = (const float*)d_in[22];
    float* out = (float*)d_out;

    float *feat, *res, *tmp;
    uint32_t *Whi, *Wlo, *Ahi, *Alo;
    int *deg, *off, *cur, *dstA, *bsum, *foff, *fbsum, *rstart, *rlist;
    cudaGetSymbolAddress((void**)&feat, g_feat);
    cudaGetSymbolAddress((void**)&res,  g_res);
    cudaGetSymbolAddress((void**)&tmp,  g_tmp);
    cudaGetSymbolAddress((void**)&Whi,  g_Whi);
    cudaGetSymbolAddress((void**)&Wlo,  g_Wlo);
    cudaGetSymbolAddress((void**)&Ahi,  g_Ahi);
    cudaGetSymbolAddress((void**)&Alo,  g_Alo);
    cudaGetSymbolAddress((void**)&deg,  g_deg);
    cudaGetSymbolAddress((void**)&off,  g_off);
    cudaGetSymbolAddress((void**)&cur,  g_cur);
    cudaGetSymbolAddress((void**)&dstA, g_dst);
    cudaGetSymbolAddress((void**)&bsum, g_bsum);
    cudaGetSymbolAddress((void**)&foff, g_foff);
    cudaGetSymbolAddress((void**)&fbsum,g_fbsum);
    cudaGetSymbolAddress((void**)&rstart,g_rstart);
    cudaGetSymbolAddress((void**)&rlist, g_rlist);
    float* Hbuf;
    cudaGetSymbolAddress((void**)&Hbuf, g_H);

    cudaFuncSetAttribute(gemm_tc_kernel,
                         cudaFuncAttributeMaxDynamicSharedMemorySize, TC_SMEM);
    cudaFuncSetAttribute(mp_p_kernel,
                         cudaFuncAttributeMaxDynamicSharedMemorySize, MPP_SMEM);

    const int lin_grid = (NNODES * NPAIRS + 255) / 256;
    const int gn_grid  = (NNODES * 32 + 255) / 256;
    const int sw_grid  = (NSLOTS * D * NPAIRS + 255) / 256;
    const int r4_grid  = (NNODES * D + 255) / 256;
    const int e_grid   = (NEDGES + 255) / 256;
    const int zn_grid  = (SCAN_N + 255) / 256;

    auto sWp = [&](int s) { return Whi + (long)s * D * NPAIRS; };
    auto sLp = [&](int s) { return Wlo + (long)s * D * NPAIRS; };

    // ---- CSR build (edge-major) + SORTED per-type row lists ----
    zero_deg_kernel<<<zn_grid, 256>>>(deg);
    deg_kernel<<<e_grid, 256>>>(indexes, mask, deg);
    scan1_kernel<<<SCAN_NBLK, 256>>>(deg, off, bsum, 0);
    scan2_kernel<<<1, 512>>>(bsum, SCAN_NBLK);
    scan3_kernel<<<zn_grid, 256>>>(off, bsum, cur);
    fill_kernel<<<e_grid, 256>>>(indexes, mask, cur, dstA);
    scan1_kernel<<<SCAN_NBLK, 256>>>(deg, foff, fbsum, 1);
    scan2_kernel<<<1, 512>>>(fbsum, SCAN_NBLK);
    scan3f_kernel<<<zn_grid, 256>>>(deg, foff, fbsum, rlist, rstart);

    // ---- pre-split weights (interleaved) ----
    split_w_kernel<<<sw_grid, 256>>>(in2_W, seg2_W, meta_W, ctr_W, edge_W, ctr2_W,
                                     Whi, Wlo);

    // ---- init: input + seg branches ----
    lin1_kernel<<<lin_grid, 256>>>(nodes, 0, in1_W, in1_b, Ahi, Alo);
    gemm_tc_kernel<<<TC_GRID, TC_THREADS, TC_SMEM>>>(Ahi, Alo, sWp(0), sLp(0), Hbuf, NNODES);
    lin1_kernel<<<lin_grid, 256>>>(nodes, 2, seg1_W, seg1_b, Ahi, Alo);
    gemm_tc_kernel<<<TC_GRID, TC_THREADS, TC_SMEM>>>(Ahi, Alo, sWp(1), sLp(1), res, NNODES);
    gn2_kernel<<<gn_grid, 256>>>(Hbuf, in_g, in_bg, res, seg_g, seg_bg, Ahi, Alo);

    // ---- meta ----
    gemm_tc_kernel<<<TC_GRID, TC_THREADS, TC_SMEM>>>(Ahi, Alo, sWp(2), sLp(2), tmp, NNODES);
    rank4_kernel<<<r4_grid, 256>>>(nodes, meta_W, tmp);
    gn_kernel<<<gn_grid, 256>>>(tmp, meta_g, meta_bg, nullptr, nullptr, res,
                                Ahi, Alo, tmp, 1);

    // ---- 4 message-passing layers ----
    for (int i = 0; i < 4; i++) {
        mp_p_kernel<<<MPP_GRID, MPP_THREADS, MPP_SMEM>>>(Ahi, Alo, Whi, Wlo, i,
                                                         off, deg, dstA, rstart, rlist,
                                                         tmp, NNODES);
        gn_kernel<<<gn_grid, 256>>>(tmp, norm_g + i * D, norm_bg + i * D,
                                    nullptr, nullptr, nullptr, Ahi, Alo, nullptr, 1);
        gemm_tc_kernel<<<TC_GRID, TC_THREADS, TC_SMEM>>>(
            Ahi, Alo, sWp(63 + i), sLp(63 + i), tmp, NNODES);
        gn_kernel<<<gn_grid, 256>>>(tmp, ctr2_g + i * D, ctr2_bg + i * D,
                                    res, (i == 3) ? feat : nullptr,
                                    (i < 3) ? res : nullptr, Ahi, Alo,
                                    (i < 3) ? tmp : nullptr, 1);
    }

    // ---- outputs ----
    int total = NNODES * D + NNODES * 2;
    copy_out_kernel<<<(total + 255) / 256, 256>>>(feat, nodes, out);
}